// round 5
// baseline (speedup 1.0000x reference)
#include <cuda_runtime.h>
#include <cstdint>

#define N_NODES 100000
#define N_EDGES 1600000
// IN_F = HID_F = 128, OUT_F = 64

#if defined(__CUDA_ARCH_FEAT_SM103_ALL)
#define HAS_TC 1
#else
#define HAS_TC 0
#endif

// chunking: 8 chunks x 98 tiles x 128 rows
#define NCH 8
#define CH_TILES 98
#define CH_ROWS (CH_TILES * 128)   // 12544
#define TOT_TILES ((N_NODES + 127) / 128)  // 782

// ---------------- scratch (device globals; no allocation allowed) ----------
__device__ int   g_deg[N_NODES];
__device__ int   g_off[N_NODES];
__device__ int   g_cur[N_NODES];
__device__ int   g_csr[N_EDGES];
__device__ int   g_bsum[128];
__device__ float g_neigh1[(size_t)N_NODES * 128];  // mean of input features
__device__ float g_h[(size_t)N_NODES * 128];       // relu(layer1)
__device__ float g_sp2[(size_t)N_NODES * 128];     // [h@W2_self | h@W2_neigh]
__device__ float g_W1cat[128 * 256];               // B^T layer1: [n][k] (k<128 self, else neigh)
__device__ float g_W2cat[128 * 128];               // B^T layer2: [n][k]

// ---------------- generic helpers -------------------------------------------
__device__ __forceinline__ uint32_t smem_u32(const void* p) {
    uint32_t a;
    asm("{ .reg .u64 t; cvta.to.shared.u64 t, %1; cvt.u32.u64 %0, t; }" : "=r"(a) : "l"(p));
    return a;
}
__device__ __forceinline__ float tf32r(float x) {
    uint32_t u;
    asm("cvt.rna.tf32.f32 %0, %1;" : "=r"(u) : "f"(x));
    return __uint_as_float(u);
}

#if HAS_TC
__device__ __forceinline__ uint32_t elect_one() {
    uint32_t p;
    asm volatile("{ .reg .pred p; elect.sync _|p, 0xFFFFFFFF; selp.b32 %0, 1, 0, p; }" : "=r"(p));
    return p;
}
#define MBAR_INIT(addr, cnt) \
    asm volatile("mbarrier.init.shared.b64 [%0], %1;" :: "r"(addr), "r"(cnt) : "memory")
__device__ __forceinline__ void mbar_wait(uint32_t addr, int phase) {
    asm volatile(
        "{\n\t.reg .pred P;\n\t"
        "WL_%=:\n\t"
        "mbarrier.try_wait.parity.acquire.cta.shared::cta.b64 P, [%0], %1, 0x989680;\n\t"
        "@P bra.uni WD_%=;\n\t"
        "bra.uni WL_%=;\n\t"
        "WD_%=:\n\t}"
        :: "r"(addr), "r"(phase) : "memory");
}
#define TC_ALLOC(ctrl, n) \
    asm volatile("tcgen05.alloc.cta_group::1.sync.aligned.shared::cta.b32 [%0], %1;" :: "r"(ctrl), "r"(n) : "memory")
#define TC_RELINQ() \
    asm volatile("tcgen05.relinquish_alloc_permit.cta_group::1.sync.aligned;")
#define TC_DEALLOC(t, n) \
    asm volatile("tcgen05.dealloc.cta_group::1.sync.aligned.b32 %0, %1;" :: "r"(t), "r"(n))
#define TC_COMMIT(mb) \
    asm volatile("tcgen05.commit.cta_group::1.mbarrier::arrive::one.shared::cluster.b64 [%0];" :: "r"(mb) : "memory")
#define TC_FENCE_AFTER()  asm volatile("tcgen05.fence::after_thread_sync;" ::: "memory")
#define TC_FENCE_BEFORE() asm volatile("tcgen05.fence::before_thread_sync;" ::: "memory")
#define TC_WAIT_LD()      asm volatile("tcgen05.wait::ld.sync.aligned;" ::: "memory")
#define FENCE_ASYNC()     asm volatile("fence.proxy.async.shared::cta;" ::: "memory")

__device__ __forceinline__ void tc_mma_tf32_ss(uint32_t d_tmem, uint64_t a_desc,
                                               uint64_t b_desc, uint32_t idesc, bool acc) {
    uint32_t en = acc ? 1u : 0u;
    asm volatile(
        "{\n\t.reg .pred p;\n\t"
        "setp.ne.u32 p, %4, 0;\n\t"
        "tcgen05.mma.cta_group::1.kind::tf32 [%0], %1, %2, %3, p;\n\t}"
        :: "r"(d_tmem), "l"(a_desc), "l"(b_desc), "r"(idesc), "r"(en) : "memory");
}

#define TC_LD_X32(r, a) \
    asm volatile( \
        "tcgen05.ld.sync.aligned.32x32b.x32.b32 " \
        "{%0,%1,%2,%3,%4,%5,%6,%7,%8,%9,%10,%11,%12,%13,%14,%15," \
        "%16,%17,%18,%19,%20,%21,%22,%23,%24,%25,%26,%27,%28,%29,%30,%31}, [%32];" \
        : "=r"((r)[0]),"=r"((r)[1]),"=r"((r)[2]),"=r"((r)[3]),"=r"((r)[4]),"=r"((r)[5]),"=r"((r)[6]),"=r"((r)[7]), \
          "=r"((r)[8]),"=r"((r)[9]),"=r"((r)[10]),"=r"((r)[11]),"=r"((r)[12]),"=r"((r)[13]),"=r"((r)[14]),"=r"((r)[15]), \
          "=r"((r)[16]),"=r"((r)[17]),"=r"((r)[18]),"=r"((r)[19]),"=r"((r)[20]),"=r"((r)[21]),"=r"((r)[22]),"=r"((r)[23]), \
          "=r"((r)[24]),"=r"((r)[25]),"=r"((r)[26]),"=r"((r)[27]),"=r"((r)[28]),"=r"((r)[29]),"=r"((r)[30]),"=r"((r)[31]) \
        : "r"(a))

// SW128 K-major descriptor: layout=2, version=1, SBO=64, LBO=1
__device__ __forceinline__ uint64_t mk_desc(uint32_t addr) {
    return ((uint64_t)2 << 61) | ((uint64_t)1 << 46) | ((uint64_t)64 << 32) |
           ((uint64_t)1 << 16) | (((uint64_t)addr >> 4) & 0x3FFF);
}

// idesc: dtype=F32, atype=TF32, btype=TF32, N=128, M=128
#define IDESC_TF32 ((1u << 4) | (2u << 7) | (2u << 10) | (16u << 17) | (8u << 24))
#endif  // HAS_TC

// ---------------- CSR build -------------------------------------------------
__global__ void k_zero_deg() {
    int i = blockIdx.x * blockDim.x + threadIdx.x;
    if (i < N_NODES) g_deg[i] = 0;
}

__global__ void k_hist(const int* __restrict__ dst) {
    int i = blockIdx.x * blockDim.x + threadIdx.x;
    if (i < N_EDGES) atomicAdd(&g_deg[dst[i]], 1);
}

__global__ void k_scan1() {
    __shared__ int s[1024];
    int tid = threadIdx.x;
    int i = blockIdx.x * 1024 + tid;
    int v = (i < N_NODES) ? g_deg[i] : 0;
    s[tid] = v;
    __syncthreads();
#pragma unroll
    for (int off = 1; off < 1024; off <<= 1) {
        int t = (tid >= off) ? s[tid - off] : 0;
        __syncthreads();
        s[tid] += t;
        __syncthreads();
    }
    if (i < N_NODES) g_off[i] = s[tid] - v;
    if (tid == 1023) g_bsum[blockIdx.x] = s[tid];
}

__global__ void k_scan2(int nb) {
    __shared__ int s[128];
    int tid = threadIdx.x;
    int v = (tid < nb) ? g_bsum[tid] : 0;
    s[tid] = v;
    __syncthreads();
#pragma unroll
    for (int off = 1; off < 128; off <<= 1) {
        int t = (tid >= off) ? s[tid - off] : 0;
        __syncthreads();
        s[tid] += t;
        __syncthreads();
    }
    if (tid < nb) g_bsum[tid] = s[tid] - v;
}

__global__ void k_scan3() {
    int i = blockIdx.x * blockDim.x + threadIdx.x;
    if (i < N_NODES) {
        int o = g_off[i] + g_bsum[i >> 10];
        g_off[i] = o;
        g_cur[i] = o;
    }
}

__global__ void k_fill(const int* __restrict__ src, const int* __restrict__ dst) {
    int i = blockIdx.x * blockDim.x + threadIdx.x;
    if (i < N_EDGES) {
        int p = atomicAdd(&g_cur[dst[i]], 1);
        g_csr[p] = src[i];
    }
}

// pack weights transposed ([n][k])
__global__ void k_pack1(const float* __restrict__ Ws, const float* __restrict__ Wn) {
    int i = blockIdx.x * blockDim.x + threadIdx.x;  // 128*256
    if (i < 128 * 256) {
        int n = i >> 8, k = i & 255;
        g_W1cat[n * 256 + k] = (k < 128) ? Ws[k * 128 + n] : Wn[(k - 128) * 128 + n];
    }
}
__global__ void k_pack2(const float* __restrict__ Ws, const float* __restrict__ Wn) {
    int i = blockIdx.x * blockDim.x + threadIdx.x;  // 128*128
    if (i < 128 * 128) {
        int n = i >> 7, k = i & 127;
        g_W2cat[n * 128 + k] = (n < 64) ? Ws[k * 64 + n] : Wn[k * 64 + (n - 64)];
    }
}

// ---------------- aggregation (warp per destination node) -------------------
// chunked: mean of feat over in-neighbors -> g_neigh1, rows [rb, re)
__global__ void k_agg_feat(const float* __restrict__ feat, int rb, int re) {
    int w = rb + ((blockIdx.x * blockDim.x + threadIdx.x) >> 5);
    int lane = threadIdx.x & 31;
    if (w >= re) return;
    int beg = g_off[w];
    int d = g_deg[w];
    int end = beg + d;
    float4 acc = make_float4(0.f, 0.f, 0.f, 0.f);
    int e = beg;
    for (; e + 1 < end; e += 2) {
        int s0 = g_csr[e];
        int s1 = g_csr[e + 1];
        float4 v0 = *(const float4*)(feat + (size_t)s0 * 128 + lane * 4);
        float4 v1 = *(const float4*)(feat + (size_t)s1 * 128 + lane * 4);
        acc.x += v0.x + v1.x;
        acc.y += v0.y + v1.y;
        acc.z += v0.z + v1.z;
        acc.w += v0.w + v1.w;
    }
    if (e < end) {
        int s0 = g_csr[e];
        float4 v0 = *(const float4*)(feat + (size_t)s0 * 128 + lane * 4);
        acc.x += v0.x; acc.y += v0.y; acc.z += v0.z; acc.w += v0.w;
    }
    float inv = (d > 0) ? 1.0f / (float)d : 0.0f;
    acc.x *= inv; acc.y *= inv; acc.z *= inv; acc.w *= inv;
    *(float4*)(g_neigh1 + (size_t)w * 128 + lane * 4) = acc;
}

// final: out[v][c] = sp2[v][c] + mean_u sp2[u][64+c] + b2[c]
__global__ void k_agg2(const float* __restrict__ b2, float* __restrict__ out) {
    int w = (blockIdx.x * blockDim.x + threadIdx.x) >> 5;
    int lane = threadIdx.x & 31;
    if (w >= N_NODES) return;
    int beg = g_off[w];
    int d = g_deg[w];
    int end = beg + d;
    float2 acc = make_float2(0.f, 0.f);
    int e = beg;
    for (; e + 1 < end; e += 2) {
        int s0 = g_csr[e];
        int s1 = g_csr[e + 1];
        float2 v0 = *(const float2*)(g_sp2 + (size_t)s0 * 128 + 64 + lane * 2);
        float2 v1 = *(const float2*)(g_sp2 + (size_t)s1 * 128 + 64 + lane * 2);
        acc.x += v0.x + v1.x;
        acc.y += v0.y + v1.y;
    }
    if (e < end) {
        int s0 = g_csr[e];
        float2 v0 = *(const float2*)(g_sp2 + (size_t)s0 * 128 + 64 + lane * 2);
        acc.x += v0.x; acc.y += v0.y;
    }
    float inv = (d > 0) ? 1.0f / (float)d : 0.0f;
    float2 self = *(const float2*)(g_sp2 + (size_t)w * 128 + lane * 2);
    float2 bb = *(const float2*)(b2 + lane * 2);
    float2 o;
    o.x = self.x + acc.x * inv + bb.x;
    o.y = self.y + acc.y * inv + bb.y;
    *(float2*)(out + (size_t)w * 64 + lane * 2) = o;
}

// ---------------- GEMM (tcgen05 3xTF32 on sm_103a; FFMA fallback otherwise) --
// LAYER 1: g_h = relu([feat | g_neigh1] @ W1cat^T + b1)   (M tile 128, N=128, K=256)
// LAYER 2: g_sp2 = g_h @ W2cat^T                          (K=128)
#define GEMM_SMEM (1024 + 4 * 16384)

template <int KTOT, int LAYER>
__global__ __launch_bounds__(256) void k_gemm(const float* __restrict__ A0,
                                              const float* __restrict__ bias, int tile0) {
    extern __shared__ __align__(1024) char smem[];
    const int tid = threadIdx.x;
    const int row0 = (tile0 + blockIdx.x) * 128;
    float* C = (LAYER == 1) ? g_h : g_sp2;
    const float* Wb = (LAYER == 1) ? g_W1cat : g_W2cat;

#if HAS_TC
    const uint32_t sb = smem_u32(smem);
    const uint32_t ctrl = sb;
    const uint32_t mb = sb + 16;
    const uint32_t smAh = sb + 1024;
    const uint32_t smAl = smAh + 16384;
    const uint32_t smBh = smAl + 16384;
    const uint32_t smBl = smBh + 16384;
    char* pAh = smem + 1024;
    char* pAl = pAh + 16384;
    char* pBh = pAl + 16384;
    char* pBl = pBh + 16384;

    const int wid = tid >> 5;
    const int lane = tid & 31;

    if (wid == 0) {
        TC_ALLOC(ctrl, 128);
        TC_RELINQ();
    }
    if (tid == 0) MBAR_INIT(mb, 1);
    __syncthreads();
    uint32_t tmem;
    asm volatile("ld.shared.b32 %0, [%1];" : "=r"(tmem) : "r"(ctrl));

    const int NC = KTOT / 32;
    int ph = 0;

    for (int c = 0; c < NC; c++) {
        if (c > 0) { mbar_wait(mb, ph); ph ^= 1; }
        const int k0 = c * 32;
        const float* Aab;
        int kl;
        if (LAYER == 1) {
            if (k0 < 128) { Aab = A0; kl = k0; }
            else          { Aab = g_neigh1; kl = k0 - 128; }
        } else {
            Aab = g_h; kl = k0;
        }

#pragma unroll
        for (int i = 0; i < 4; i++) {
            int slot = tid * 4 + i;       // 0..1023
            int rw = slot >> 3;           // 0..127
            int c16 = slot & 7;           // 0..7
            uint32_t bo = rw * 128 + c16 * 16;
            uint32_t sw = bo ^ ((bo >> 3) & 0x70);
            // A (tail-guarded)
            float4 av = make_float4(0.f, 0.f, 0.f, 0.f);
            int r = row0 + rw;
            if (r < N_NODES) av = *(const float4*)(Aab + (size_t)r * 128 + kl + c16 * 4);
            float4 ah, al;
            ah.x = tf32r(av.x); al.x = tf32r(av.x - ah.x);
            ah.y = tf32r(av.y); al.y = tf32r(av.y - ah.y);
            ah.z = tf32r(av.z); al.z = tf32r(av.z - ah.z);
            ah.w = tf32r(av.w); al.w = tf32r(av.w - ah.w);
            *(float4*)(pAh + sw) = ah;
            *(float4*)(pAl + sw) = al;
            // B
            float4 bv = *(const float4*)(Wb + (size_t)rw * KTOT + k0 + c16 * 4);
            float4 bh, bl;
            bh.x = tf32r(bv.x); bl.x = tf32r(bv.x - bh.x);
            bh.y = tf32r(bv.y); bl.y = tf32r(bv.y - bh.y);
            bh.z = tf32r(bv.z); bl.z = tf32r(bv.z - bh.z);
            bh.w = tf32r(bv.w); bl.w = tf32r(bv.w - bh.w);
            *(float4*)(pBh + sw) = bh;
            *(float4*)(pBl + sw) = bl;
        }
        FENCE_ASYNC();
        __syncthreads();
        if (wid == 0) {
            if (elect_one()) {
                uint64_t adh = mk_desc(smAh), adl = mk_desc(smAl);
                uint64_t bdh = mk_desc(smBh), bdl = mk_desc(smBl);
#pragma unroll
                for (int s = 0; s < 4; s++) {
                    tc_mma_tf32_ss(tmem, adh + s * 2, bdh + s * 2, IDESC_TF32, !(c == 0 && s == 0));
                    tc_mma_tf32_ss(tmem, adh + s * 2, bdl + s * 2, IDESC_TF32, true);
                    tc_mma_tf32_ss(tmem, adl + s * 2, bdh + s * 2, IDESC_TF32, true);
                }
                TC_COMMIT(mb);
            }
        }
    }
    mbar_wait(mb, ph);
    TC_FENCE_AFTER();

    // epilogue: warps 0..3 each cover 32 M-rows
    if (wid < 4) {
        int r = row0 + wid * 32 + lane;
#pragma unroll
        for (int off = 0; off < 128; off += 32) {
            uint32_t dr[32];
            TC_LD_X32(dr, tmem + off);
            TC_WAIT_LD();
            if (r < N_NODES) {
                float v[32];
#pragma unroll
                for (int j = 0; j < 32; j++) {
                    float x = __uint_as_float(dr[j]);
                    if (LAYER == 1) x = fmaxf(x + bias[off + j], 0.f);
                    v[j] = x;
                }
#pragma unroll
                for (int q = 0; q < 8; q++)
                    *(float4*)(C + (size_t)r * 128 + off + q * 4) =
                        make_float4(v[q * 4], v[q * 4 + 1], v[q * 4 + 2], v[q * 4 + 3]);
            }
        }
        TC_FENCE_BEFORE();
    }
    __syncthreads();
    if (wid == 0) TC_DEALLOC(tmem, 128);

#else  // ---------------- FFMA fallback (non-sm_103a pass; never runs on GB300)
    float* As = (float*)(smem + 1024);                     // [16][136]
    float* Bs = (float*)(smem + 1024 + 16 * 136 * 4);      // [16][132]
    const int trow = tid >> 4;
    const int tcol = tid & 15;

    float acc[8][8];
#pragma unroll
    for (int i = 0; i < 8; i++)
#pragma unroll
        for (int j = 0; j < 8; j++) acc[i][j] = 0.f;

    for (int k0 = 0; k0 < KTOT; k0 += 16) {
        const float* Aab;
        int kl;
        if (LAYER == 1) {
            if (k0 < 128) { Aab = A0; kl = k0; }
            else          { Aab = g_neigh1; kl = k0 - 128; }
        } else {
            Aab = g_h; kl = k0;
        }
        {
            int lr = tid >> 1;
            int lc = (tid & 1) * 8;
            int r = row0 + lr;
            float4 v0 = make_float4(0.f, 0.f, 0.f, 0.f), v1 = v0;
            if (r < N_NODES) {
                v0 = *(const float4*)(Aab + (size_t)r * 128 + kl + lc);
                v1 = *(const float4*)(Aab + (size_t)r * 128 + kl + lc + 4);
            }
            As[(lc + 0) * 136 + lr] = v0.x;
            As[(lc + 1) * 136 + lr] = v0.y;
            As[(lc + 2) * 136 + lr] = v0.z;
            As[(lc + 3) * 136 + lr] = v0.w;
            As[(lc + 4) * 136 + lr] = v1.x;
            As[(lc + 5) * 136 + lr] = v1.y;
            As[(lc + 6) * 136 + lr] = v1.z;
            As[(lc + 7) * 136 + lr] = v1.w;
        }
        {
            int n = tid >> 1;
            int ks = (tid & 1) * 8;
            float4 v0 = *(const float4*)(Wb + (size_t)n * KTOT + k0 + ks);
            float4 v1 = *(const float4*)(Wb + (size_t)n * KTOT + k0 + ks + 4);
            Bs[(ks + 0) * 132 + n] = v0.x;
            Bs[(ks + 1) * 132 + n] = v0.y;
            Bs[(ks + 2) * 132 + n] = v0.z;
            Bs[(ks + 3) * 132 + n] = v0.w;
            Bs[(ks + 4) * 132 + n] = v1.x;
            Bs[(ks + 5) * 132 + n] = v1.y;
            Bs[(ks + 6) * 132 + n] = v1.z;
            Bs[(ks + 7) * 132 + n] = v1.w;
        }
        __syncthreads();
#pragma unroll
        for (int kk = 0; kk < 16; kk++) {
            float a[8], b[8];
#pragma unroll
            for (int i = 0; i < 8; i++) a[i] = As[kk * 136 + trow * 8 + i];
#pragma unroll
            for (int j = 0; j < 8; j++) b[j] = Bs[kk * 132 + tcol * 8 + j];
#pragma unroll
            for (int i = 0; i < 8; i++)
#pragma unroll
                for (int j = 0; j < 8; j++) acc[i][j] += a[i] * b[j];
        }
        __syncthreads();
    }
#pragma unroll
    for (int i = 0; i < 8; i++) {
        int r = row0 + trow * 8 + i;
        if (r >= N_NODES) continue;
        float o[8];
#pragma unroll
        for (int j = 0; j < 8; j++) {
            float v = acc[i][j];
            if (LAYER == 1) {
                v += bias[tcol * 8 + j];
                v = fmaxf(v, 0.f);
            }
            o[j] = v;
        }
        *(float4*)(C + (size_t)r * 128 + tcol * 8)     = make_float4(o[0], o[1], o[2], o[3]);
        *(float4*)(C + (size_t)r * 128 + tcol * 8 + 4) = make_float4(o[4], o[5], o[6], o[7]);
    }
#endif
}

// ---------------- launch -----------------------------------------------------
extern "C" void kernel_launch(void* const* d_in, const int* in_sizes, int n_in,
                              void* d_out, int out_size) {
    const float* feat = (const float*)d_in[0];
    const int*   esrc = (const int*)d_in[1];
    const int*   edst = (const int*)d_in[2];
    const float* W1s  = (const float*)d_in[3];
    const float* W1n  = (const float*)d_in[4];
    const float* b1   = (const float*)d_in[5];
    const float* W2s  = (const float*)d_in[6];
    const float* W2n  = (const float*)d_in[7];
    const float* b2   = (const float*)d_in[8];
    float* out = (float*)d_out;

    static cudaStream_t s1 = nullptr;
    static cudaEvent_t e0 = nullptr, eCSR = nullptr;
    static cudaEvent_t eA[NCH];
    if (!s1) {
        cudaStreamCreateWithFlags(&s1, cudaStreamNonBlocking);
        cudaEventCreateWithFlags(&e0, cudaEventDisableTiming);
        cudaEventCreateWithFlags(&eCSR, cudaEventDisableTiming);
        for (int c = 0; c < NCH; c++) cudaEventCreateWithFlags(&eA[c], cudaEventDisableTiming);
    }

    cudaFuncSetAttribute(k_gemm<256, 1>, cudaFuncAttributeMaxDynamicSharedMemorySize, GEMM_SMEM);
    cudaFuncSetAttribute(k_gemm<128, 2>, cudaFuncAttributeMaxDynamicSharedMemorySize, GEMM_SMEM);

    const int TB = 256;

    // ---- fork s1 from stream 0
    cudaEventRecord(e0, 0);
    cudaStreamWaitEvent(s1, e0, 0);

    // ---- s1: weight packs (graph-independent)
    k_pack1<<<(128 * 256 + TB - 1) / TB, TB, 0, s1>>>(W1s, W1n);
    k_pack2<<<(128 * 128 + TB - 1) / TB, TB, 0, s1>>>(W2s, W2n);

    // ---- stream 0: CSR build
    k_zero_deg<<<(N_NODES + TB - 1) / TB, TB>>>();
    k_hist<<<(N_EDGES + TB - 1) / TB, TB>>>(edst);
    int nb = (N_NODES + 1023) / 1024;  // 98
    k_scan1<<<nb, 1024>>>();
    k_scan2<<<1, 128>>>(nb);
    k_scan3<<<(N_NODES + TB - 1) / TB, TB>>>();
    k_fill<<<(N_EDGES + TB - 1) / TB, TB>>>(esrc, edst);
    cudaEventRecord(eCSR, 0);

    // ---- s1: chunked feat aggregation (needs CSR)
    cudaStreamWaitEvent(s1, eCSR, 0);
    for (int c = 0; c < NCH; c++) {
        int rb = c * CH_ROWS;
        int re = (rb + CH_ROWS < N_NODES) ? rb + CH_ROWS : N_NODES;
        int nw = re - rb;
        k_agg_feat<<<(nw * 32 + TB - 1) / TB, TB, 0, s1>>>(feat, rb, re);
        cudaEventRecord(eA[c], s1);
    }

    // ---- stream 0: per-chunk GEMM1 (K=256, bias+relu) then GEMM2 (pipelined vs gather)
    for (int c = 0; c < NCH; c++) {
        int t0 = c * CH_TILES;
        int tc = (t0 + CH_TILES < TOT_TILES) ? CH_TILES : TOT_TILES - t0;
        cudaStreamWaitEvent(0, eA[c], 0);
        k_gemm<256, 1><<<tc, 256, GEMM_SMEM>>>(feat, b1, t0);
        k_gemm<128, 2><<<tc, 256, GEMM_SMEM>>>(nullptr, nullptr, t0);
    }

    // ---- stream 0: final aggregation (needs all sp2; in-order after last GEMM2)
    k_agg2<<<(N_NODES * 32 + TB - 1) / TB, TB>>>(b2, out);
}

// round 6
// speedup vs baseline: 1.9912x; 1.9912x over previous
#include <cuda_runtime.h>
#include <cuda_fp16.h>
#include <cstdint>

#define N_NODES 100000
#define N_EDGES 1600000
// IN_F = HID_F = 128, OUT_F = 64

#if defined(__CUDA_ARCH_FEAT_SM103_ALL)
#define HAS_TC 1
#else
#define HAS_TC 0
#endif

#define TOT_TILES ((N_NODES + 127) / 128)  // 782

// ---------------- scratch (device globals; no allocation allowed) ----------
__device__ int    g_deg[N_NODES];
__device__ int    g_off[N_NODES];
__device__ int    g_cur[N_NODES];
__device__ int    g_csr[N_EDGES];
__device__ int    g_bsum[128];
__device__ float  g_sp1s[(size_t)N_NODES * 128];   // feat @ W1_self (fp32)
__device__ __half g_sp1nH[(size_t)N_NODES * 128];  // feat @ W1_neigh (fp16)
__device__ float  g_h[(size_t)N_NODES * 128];      // relu(layer1)
__device__ float  g_sp2s[(size_t)N_NODES * 64];    // h @ W2_self (fp32)
__device__ __half g_sp2nH[(size_t)N_NODES * 64];   // h @ W2_neigh (fp16)
__device__ float  g_W1cat[256 * 128];              // B^T layer1: [n][k], n<128 self, else neigh
__device__ float  g_W2cat[128 * 128];              // B^T layer2: [n][k], n<64 self, else neigh

// ---------------- generic helpers -------------------------------------------
__device__ __forceinline__ uint32_t smem_u32(const void* p) {
    uint32_t a;
    asm("{ .reg .u64 t; cvta.to.shared.u64 t, %1; cvt.u32.u64 %0, t; }" : "=r"(a) : "l"(p));
    return a;
}
__device__ __forceinline__ float tf32r(float x) {
    uint32_t u;
    asm("cvt.rna.tf32.f32 %0, %1;" : "=r"(u) : "f"(x));
    return __uint_as_float(u);
}

#if HAS_TC
__device__ __forceinline__ uint32_t elect_one() {
    uint32_t p;
    asm volatile("{ .reg .pred p; elect.sync _|p, 0xFFFFFFFF; selp.b32 %0, 1, 0, p; }" : "=r"(p));
    return p;
}
#define MBAR_INIT(addr, cnt) \
    asm volatile("mbarrier.init.shared.b64 [%0], %1;" :: "r"(addr), "r"(cnt) : "memory")
__device__ __forceinline__ void mbar_wait(uint32_t addr, int phase) {
    asm volatile(
        "{\n\t.reg .pred P;\n\t"
        "WL_%=:\n\t"
        "mbarrier.try_wait.parity.acquire.cta.shared::cta.b64 P, [%0], %1, 0x989680;\n\t"
        "@P bra.uni WD_%=;\n\t"
        "bra.uni WL_%=;\n\t"
        "WD_%=:\n\t}"
        :: "r"(addr), "r"(phase) : "memory");
}
#define TC_ALLOC(ctrl, n) \
    asm volatile("tcgen05.alloc.cta_group::1.sync.aligned.shared::cta.b32 [%0], %1;" :: "r"(ctrl), "r"(n) : "memory")
#define TC_RELINQ() \
    asm volatile("tcgen05.relinquish_alloc_permit.cta_group::1.sync.aligned;")
#define TC_DEALLOC(t, n) \
    asm volatile("tcgen05.dealloc.cta_group::1.sync.aligned.b32 %0, %1;" :: "r"(t), "r"(n))
#define TC_COMMIT(mb) \
    asm volatile("tcgen05.commit.cta_group::1.mbarrier::arrive::one.shared::cluster.b64 [%0];" :: "r"(mb) : "memory")
#define TC_FENCE_AFTER()  asm volatile("tcgen05.fence::after_thread_sync;" ::: "memory")
#define TC_FENCE_BEFORE() asm volatile("tcgen05.fence::before_thread_sync;" ::: "memory")
#define TC_WAIT_LD()      asm volatile("tcgen05.wait::ld.sync.aligned;" ::: "memory")
#define FENCE_ASYNC()     asm volatile("fence.proxy.async.shared::cta;" ::: "memory")

__device__ __forceinline__ void tc_mma_tf32_ss(uint32_t d_tmem, uint64_t a_desc,
                                               uint64_t b_desc, uint32_t idesc, bool acc) {
    uint32_t en = acc ? 1u : 0u;
    asm volatile(
        "{\n\t.reg .pred p;\n\t"
        "setp.ne.u32 p, %4, 0;\n\t"
        "tcgen05.mma.cta_group::1.kind::tf32 [%0], %1, %2, %3, p;\n\t}"
        :: "r"(d_tmem), "l"(a_desc), "l"(b_desc), "r"(idesc), "r"(en) : "memory");
}

#define TC_LD_X32(r, a) \
    asm volatile( \
        "tcgen05.ld.sync.aligned.32x32b.x32.b32 " \
        "{%0,%1,%2,%3,%4,%5,%6,%7,%8,%9,%10,%11,%12,%13,%14,%15," \
        "%16,%17,%18,%19,%20,%21,%22,%23,%24,%25,%26,%27,%28,%29,%30,%31}, [%32];" \
        : "=r"((r)[0]),"=r"((r)[1]),"=r"((r)[2]),"=r"((r)[3]),"=r"((r)[4]),"=r"((r)[5]),"=r"((r)[6]),"=r"((r)[7]), \
          "=r"((r)[8]),"=r"((r)[9]),"=r"((r)[10]),"=r"((r)[11]),"=r"((r)[12]),"=r"((r)[13]),"=r"((r)[14]),"=r"((r)[15]), \
          "=r"((r)[16]),"=r"((r)[17]),"=r"((r)[18]),"=r"((r)[19]),"=r"((r)[20]),"=r"((r)[21]),"=r"((r)[22]),"=r"((r)[23]), \
          "=r"((r)[24]),"=r"((r)[25]),"=r"((r)[26]),"=r"((r)[27]),"=r"((r)[28]),"=r"((r)[29]),"=r"((r)[30]),"=r"((r)[31]) \
        : "r"(a))

// SW128 K-major descriptor: layout=2, version=1, SBO=64, LBO=1
__device__ __forceinline__ uint64_t mk_desc(uint32_t addr) {
    return ((uint64_t)2 << 61) | ((uint64_t)1 << 46) | ((uint64_t)64 << 32) |
           ((uint64_t)1 << 16) | (((uint64_t)addr >> 4) & 0x3FFF);
}

// idesc: dtype=F32, atype=TF32, btype=TF32, N=128, M=128
#define IDESC_TF32 ((1u << 4) | (2u << 7) | (2u << 10) | (16u << 17) | (8u << 24))
#endif  // HAS_TC

// ---------------- CSR build -------------------------------------------------
__global__ void k_zero_deg() {
    int i = blockIdx.x * blockDim.x + threadIdx.x;
    if (i < N_NODES) g_deg[i] = 0;
}

__global__ void k_hist(const int* __restrict__ dst) {
    int i = blockIdx.x * blockDim.x + threadIdx.x;
    if (i < N_EDGES) atomicAdd(&g_deg[dst[i]], 1);
}

__global__ void k_scan1() {
    __shared__ int s[1024];
    int tid = threadIdx.x;
    int i = blockIdx.x * 1024 + tid;
    int v = (i < N_NODES) ? g_deg[i] : 0;
    s[tid] = v;
    __syncthreads();
#pragma unroll
    for (int off = 1; off < 1024; off <<= 1) {
        int t = (tid >= off) ? s[tid - off] : 0;
        __syncthreads();
        s[tid] += t;
        __syncthreads();
    }
    if (i < N_NODES) g_off[i] = s[tid] - v;
    if (tid == 1023) g_bsum[blockIdx.x] = s[tid];
}

__global__ void k_scan2(int nb) {
    __shared__ int s[128];
    int tid = threadIdx.x;
    int v = (tid < nb) ? g_bsum[tid] : 0;
    s[tid] = v;
    __syncthreads();
#pragma unroll
    for (int off = 1; off < 128; off <<= 1) {
        int t = (tid >= off) ? s[tid - off] : 0;
        __syncthreads();
        s[tid] += t;
        __syncthreads();
    }
    if (tid < nb) g_bsum[tid] = s[tid] - v;
}

__global__ void k_scan3() {
    int i = blockIdx.x * blockDim.x + threadIdx.x;
    if (i < N_NODES) {
        int o = g_off[i] + g_bsum[i >> 10];
        g_off[i] = o;
        g_cur[i] = o;
    }
}

__global__ void k_fill(const int* __restrict__ src, const int* __restrict__ dst) {
    int i = blockIdx.x * blockDim.x + threadIdx.x;
    if (i < N_EDGES) {
        int p = atomicAdd(&g_cur[dst[i]], 1);
        g_csr[p] = src[i];
    }
}

// pack both weight matrices transposed ([n][k])
__global__ void k_pack(const float* __restrict__ W1s, const float* __restrict__ W1n,
                       const float* __restrict__ W2s, const float* __restrict__ W2n) {
    int i = blockIdx.x * blockDim.x + threadIdx.x;  // 32768 + 16384
    if (i < 256 * 128) {
        int n = i >> 7, k = i & 127;
        g_W1cat[i] = (n < 128) ? W1s[k * 128 + n] : W1n[k * 128 + (n - 128)];
    } else if (i < 256 * 128 + 128 * 128) {
        int j = i - 256 * 128;
        int n = j >> 7, k = j & 127;
        g_W2cat[j] = (n < 64) ? W2s[k * 64 + n] : W2n[k * 64 + (n - 64)];
    }
}

// ---------------- aggregation (warp per destination node) -------------------
// layer1: g_h[v] = relu(sp1s[v] + mean_u sp1nH[u] + b1)
__global__ void k_agg1(const float* __restrict__ b1) {
    int w = (blockIdx.x * blockDim.x + threadIdx.x) >> 5;
    int lane = threadIdx.x & 31;
    if (w >= N_NODES) return;
    int beg = g_off[w];
    int d = g_deg[w];
    int end = beg + d;
    float4 acc = make_float4(0.f, 0.f, 0.f, 0.f);
    int e = beg;
    for (; e + 1 < end; e += 2) {
        int s0 = g_csr[e];
        int s1 = g_csr[e + 1];
        uint2 r0 = *(const uint2*)(g_sp1nH + (size_t)s0 * 128 + lane * 4);
        uint2 r1 = *(const uint2*)(g_sp1nH + (size_t)s1 * 128 + lane * 4);
        float2 a0 = __half22float2(*(__half2*)&r0.x);
        float2 a1 = __half22float2(*(__half2*)&r0.y);
        float2 b0 = __half22float2(*(__half2*)&r1.x);
        float2 b1v = __half22float2(*(__half2*)&r1.y);
        acc.x += a0.x + b0.x;
        acc.y += a0.y + b0.y;
        acc.z += a1.x + b1v.x;
        acc.w += a1.y + b1v.y;
    }
    if (e < end) {
        int s0 = g_csr[e];
        uint2 r0 = *(const uint2*)(g_sp1nH + (size_t)s0 * 128 + lane * 4);
        float2 a0 = __half22float2(*(__half2*)&r0.x);
        float2 a1 = __half22float2(*(__half2*)&r0.y);
        acc.x += a0.x; acc.y += a0.y; acc.z += a1.x; acc.w += a1.y;
    }
    float inv = (d > 0) ? 1.0f / (float)d : 0.0f;
    float4 self = *(const float4*)(g_sp1s + (size_t)w * 128 + lane * 4);
    float4 bb = *(const float4*)(b1 + lane * 4);
    float4 o;
    o.x = fmaxf(self.x + acc.x * inv + bb.x, 0.f);
    o.y = fmaxf(self.y + acc.y * inv + bb.y, 0.f);
    o.z = fmaxf(self.z + acc.z * inv + bb.z, 0.f);
    o.w = fmaxf(self.w + acc.w * inv + bb.w, 0.f);
    *(float4*)(g_h + (size_t)w * 128 + lane * 4) = o;
}

// layer2: out[v][c] = sp2s[v][c] + mean_u sp2nH[u][c] + b2[c]
__global__ void k_agg2(const float* __restrict__ b2, float* __restrict__ out) {
    int w = (blockIdx.x * blockDim.x + threadIdx.x) >> 5;
    int lane = threadIdx.x & 31;
    if (w >= N_NODES) return;
    int beg = g_off[w];
    int d = g_deg[w];
    int end = beg + d;
    float2 acc = make_float2(0.f, 0.f);
    int e = beg;
    for (; e + 1 < end; e += 2) {
        int s0 = g_csr[e];
        int s1 = g_csr[e + 1];
        uint32_t r0 = *(const uint32_t*)(g_sp2nH + (size_t)s0 * 64 + lane * 2);
        uint32_t r1 = *(const uint32_t*)(g_sp2nH + (size_t)s1 * 64 + lane * 2);
        float2 f0 = __half22float2(*(__half2*)&r0);
        float2 f1 = __half22float2(*(__half2*)&r1);
        acc.x += f0.x + f1.x;
        acc.y += f0.y + f1.y;
    }
    if (e < end) {
        int s0 = g_csr[e];
        uint32_t r0 = *(const uint32_t*)(g_sp2nH + (size_t)s0 * 64 + lane * 2);
        float2 f0 = __half22float2(*(__half2*)&r0);
        acc.x += f0.x; acc.y += f0.y;
    }
    float inv = (d > 0) ? 1.0f / (float)d : 0.0f;
    float2 self = *(const float2*)(g_sp2s + (size_t)w * 64 + lane * 2);
    float2 bb = *(const float2*)(b2 + lane * 2);
    float2 o;
    o.x = self.x + acc.x * inv + bb.x;
    o.y = self.y + acc.y * inv + bb.y;
    *(float2*)(out + (size_t)w * 64 + lane * 2) = o;
}

// ---------------- GEMM (tcgen05 3xTF32 on sm_103a; naive fallback otherwise) -
// LAYER 1 (NT=2): [sp1s | sp1nH] = feat @ W1cat^T   (K=128, N=256)
// LAYER 2 (NT=1): [sp2s | sp2nH] = g_h @ W2cat^T    (K=128, N=128)
#define GEMM1_SMEM (1024 + 6 * 16384)
#define GEMM2_SMEM (1024 + 4 * 16384)

template <int NT, int LAYER>
__global__ __launch_bounds__(256) void k_gemm(const float* __restrict__ A0) {
    extern __shared__ __align__(1024) char smem[];
    const int tid = threadIdx.x;
    const int row0 = blockIdx.x * 128;
    const float* Wb = (LAYER == 1) ? g_W1cat : g_W2cat;
    const float* Asrc = (LAYER == 1) ? A0 : g_h;

#if HAS_TC
    const uint32_t sb = smem_u32(smem);
    const uint32_t ctrl = sb;
    const uint32_t mb = sb + 16;
    const uint32_t smAh = sb + 1024;
    const uint32_t smAl = smAh + 16384;
    uint32_t smBh[2], smBl[2];
    smBh[0] = smAl + 16384;
    smBl[0] = smBh[0] + 16384;
    smBh[1] = smBl[0] + 16384;
    smBl[1] = smBh[1] + 16384;

    const int wid = tid >> 5;
    const int lane = tid & 31;

    if (wid == 0) {
        TC_ALLOC(ctrl, NT * 128);
        TC_RELINQ();
    }
    if (tid == 0) MBAR_INIT(mb, 1);
    __syncthreads();
    uint32_t tmem;
    asm volatile("ld.shared.b32 %0, [%1];" : "=r"(tmem) : "r"(ctrl));

    int ph = 0;
    for (int c = 0; c < 4; c++) {
        if (c > 0) { mbar_wait(mb, ph); ph ^= 1; }
        const int k0 = c * 32;

#pragma unroll
        for (int i = 0; i < 4; i++) {
            int slot = tid * 4 + i;       // 0..1023
            int rw = slot >> 3;           // 0..127
            int c16 = slot & 7;           // 0..7
            uint32_t bo = rw * 128 + c16 * 16;
            uint32_t sw = bo ^ ((bo >> 3) & 0x70);
            // A (tail-guarded)
            float4 av = make_float4(0.f, 0.f, 0.f, 0.f);
            int r = row0 + rw;
            if (r < N_NODES) av = *(const float4*)(Asrc + (size_t)r * 128 + k0 + c16 * 4);
            float4 ah, al;
            ah.x = tf32r(av.x); al.x = tf32r(av.x - ah.x);
            ah.y = tf32r(av.y); al.y = tf32r(av.y - ah.y);
            ah.z = tf32r(av.z); al.z = tf32r(av.z - ah.z);
            ah.w = tf32r(av.w); al.w = tf32r(av.w - ah.w);
            *(float4*)(smem + (smAh - sb) + sw) = ah;
            *(float4*)(smem + (smAl - sb) + sw) = al;
            // B tiles
#pragma unroll
            for (int nt = 0; nt < NT; nt++) {
                float4 bv = *(const float4*)(Wb + (size_t)(nt * 128 + rw) * 128 + k0 + c16 * 4);
                float4 bh, bl;
                bh.x = tf32r(bv.x); bl.x = tf32r(bv.x - bh.x);
                bh.y = tf32r(bv.y); bl.y = tf32r(bv.y - bh.y);
                bh.z = tf32r(bv.z); bl.z = tf32r(bv.z - bh.z);
                bh.w = tf32r(bv.w); bl.w = tf32r(bv.w - bh.w);
                *(float4*)(smem + (smBh[nt] - sb) + sw) = bh;
                *(float4*)(smem + (smBl[nt] - sb) + sw) = bl;
            }
        }
        FENCE_ASYNC();
        __syncthreads();
        if (wid == 0) {
            if (elect_one()) {
                uint64_t adh = mk_desc(smAh), adl = mk_desc(smAl);
#pragma unroll
                for (int nt = 0; nt < NT; nt++) {
                    uint64_t bdh = mk_desc(smBh[nt]), bdl = mk_desc(smBl[nt]);
                    uint32_t dt = tmem + nt * 128;
#pragma unroll
                    for (int s = 0; s < 4; s++) {
                        tc_mma_tf32_ss(dt, adh + s * 2, bdh + s * 2, IDESC_TF32, !(c == 0 && s == 0));
                        tc_mma_tf32_ss(dt, adh + s * 2, bdl + s * 2, IDESC_TF32, true);
                        tc_mma_tf32_ss(dt, adl + s * 2, bdh + s * 2, IDESC_TF32, true);
                    }
                }
                TC_COMMIT(mb);
            }
        }
    }
    mbar_wait(mb, ph);
    TC_FENCE_AFTER();

    // epilogue: warps 0..3 each cover 32 M-rows
    if (wid < 4) {
        int r = row0 + wid * 32 + lane;
        if (LAYER == 1) {
            // self half (fp32) at tmem cols [0,128)
#pragma unroll
            for (int off = 0; off < 128; off += 32) {
                uint32_t dr[32];
                TC_LD_X32(dr, tmem + off);
                TC_WAIT_LD();
                if (r < N_NODES) {
#pragma unroll
                    for (int q = 0; q < 8; q++)
                        *(float4*)(g_sp1s + (size_t)r * 128 + off + q * 4) =
                            make_float4(__uint_as_float(dr[q * 4]), __uint_as_float(dr[q * 4 + 1]),
                                        __uint_as_float(dr[q * 4 + 2]), __uint_as_float(dr[q * 4 + 3]));
                }
            }
            // neigh half (fp16) at tmem cols [128,256)
#pragma unroll
            for (int off = 0; off < 128; off += 32) {
                uint32_t dr[32];
                TC_LD_X32(dr, tmem + 128 + off);
                TC_WAIT_LD();
                if (r < N_NODES) {
                    uint32_t pk[16];
#pragma unroll
                    for (int q = 0; q < 16; q++) {
                        __half2 hh = __floats2half2_rn(__uint_as_float(dr[2 * q]),
                                                       __uint_as_float(dr[2 * q + 1]));
                        pk[q] = *(uint32_t*)&hh;
                    }
#pragma unroll
                    for (int q = 0; q < 4; q++)
                        *(uint4*)(g_sp1nH + (size_t)r * 128 + off + q * 8) =
                            make_uint4(pk[q * 4], pk[q * 4 + 1], pk[q * 4 + 2], pk[q * 4 + 3]);
                }
            }
        } else {
            // self cols [0,64) fp32
#pragma unroll
            for (int off = 0; off < 64; off += 32) {
                uint32_t dr[32];
                TC_LD_X32(dr, tmem + off);
                TC_WAIT_LD();
                if (r < N_NODES) {
#pragma unroll
                    for (int q = 0; q < 8; q++)
                        *(float4*)(g_sp2s + (size_t)r * 64 + off + q * 4) =
                            make_float4(__uint_as_float(dr[q * 4]), __uint_as_float(dr[q * 4 + 1]),
                                        __uint_as_float(dr[q * 4 + 2]), __uint_as_float(dr[q * 4 + 3]));
                }
            }
            // neigh cols [64,128) fp16
#pragma unroll
            for (int off = 0; off < 64; off += 32) {
                uint32_t dr[32];
                TC_LD_X32(dr, tmem + 64 + off);
                TC_WAIT_LD();
                if (r < N_NODES) {
                    uint32_t pk[16];
#pragma unroll
                    for (int q = 0; q < 16; q++) {
                        __half2 hh = __floats2half2_rn(__uint_as_float(dr[2 * q]),
                                                       __uint_as_float(dr[2 * q + 1]));
                        pk[q] = *(uint32_t*)&hh;
                    }
#pragma unroll
                    for (int q = 0; q < 4; q++)
                        *(uint4*)(g_sp2nH + (size_t)r * 64 + off + q * 8) =
                            make_uint4(pk[q * 4], pk[q * 4 + 1], pk[q * 4 + 2], pk[q * 4 + 3]);
                }
            }
        }
        TC_FENCE_BEFORE();
    }
    __syncthreads();
    if (wid == 0) TC_DEALLOC(tmem, NT * 128);

#else  // ---------------- naive fallback (non-sm_103a pass; never runs on GB300)
    for (int e = tid; e < 128 * NT * 128; e += 256) {
        int rr = e / (NT * 128);
        int cc = e % (NT * 128);
        int r = row0 + rr;
        if (r >= N_NODES) continue;
        const float* Arow = Asrc + (size_t)r * 128;
        const float* Brow = Wb + (size_t)cc * 128;
        float s = 0.f;
        for (int k = 0; k < 128; k++) s += Arow[k] * Brow[k];
        if (LAYER == 1) {
            if (cc < 128) g_sp1s[(size_t)r * 128 + cc] = s;
            else          g_sp1nH[(size_t)r * 128 + (cc - 128)] = __float2half_rn(s);
        } else {
            if (cc < 64) g_sp2s[(size_t)r * 64 + cc] = s;
            else         g_sp2nH[(size_t)r * 64 + (cc - 64)] = __float2half_rn(s);
        }
    }
#endif
}

// ---------------- launch -----------------------------------------------------
extern "C" void kernel_launch(void* const* d_in, const int* in_sizes, int n_in,
                              void* d_out, int out_size) {
    const float* feat = (const float*)d_in[0];
    const int*   esrc = (const int*)d_in[1];
    const int*   edst = (const int*)d_in[2];
    const float* W1s  = (const float*)d_in[3];
    const float* W1n  = (const float*)d_in[4];
    const float* b1   = (const float*)d_in[5];
    const float* W2s  = (const float*)d_in[6];
    const float* W2n  = (const float*)d_in[7];
    const float* b2   = (const float*)d_in[8];
    float* out = (float*)d_out;

    static cudaStream_t s1 = nullptr;
    static cudaEvent_t e0 = nullptr, e1 = nullptr;
    if (!s1) {
        cudaStreamCreateWithFlags(&s1, cudaStreamNonBlocking);
        cudaEventCreateWithFlags(&e0, cudaEventDisableTiming);
        cudaEventCreateWithFlags(&e1, cudaEventDisableTiming);
    }

    cudaFuncSetAttribute(k_gemm<2, 1>, cudaFuncAttributeMaxDynamicSharedMemorySize, GEMM1_SMEM);
    cudaFuncSetAttribute(k_gemm<1, 2>, cudaFuncAttributeMaxDynamicSharedMemorySize, GEMM2_SMEM);

    const int TB = 256;

    // ---- fork: stream s1 does pack + layer-1 projection GEMM (graph-independent)
    cudaEventRecord(e0, 0);
    cudaStreamWaitEvent(s1, e0, 0);
    k_pack<<<(256 * 128 + 128 * 128 + TB - 1) / TB, TB, 0, s1>>>(W1s, W1n, W2s, W2n);
    k_gemm<2, 1><<<TOT_TILES, 256, GEMM1_SMEM, s1>>>(feat);
    cudaEventRecord(e1, s1);

    // ---- default stream: CSR build
    k_zero_deg<<<(N_NODES + TB - 1) / TB, TB>>>();
    k_hist<<<(N_EDGES + TB - 1) / TB, TB>>>(edst);
    int nb = (N_NODES + 1023) / 1024;  // 98
    k_scan1<<<nb, 1024>>>();
    k_scan2<<<1, 128>>>(nb);
    k_scan3<<<(N_NODES + TB - 1) / TB, TB>>>();
    k_fill<<<(N_EDGES + TB - 1) / TB, TB>>>(esrc, edst);

    // ---- join
    cudaStreamWaitEvent(0, e1, 0);

    // layer 1 aggregate (+self+bias+relu), layer 2 projection, layer 2 aggregate
    k_agg1<<<(N_NODES * 32 + TB - 1) / TB, TB>>>(b1);
    k_gemm<1, 2><<<TOT_TILES, 256, GEMM2_SMEM>>>(nullptr);
    k_agg2<<<(N_NODES * 32 + TB - 1) / TB, TB>>>(b2, out);
}

// round 7
// speedup vs baseline: 2.1807x; 1.0952x over previous
#include <cuda_runtime.h>
#include <cuda_fp16.h>
#include <cstdint>

#define N_NODES 100000
#define N_EDGES 1600000
// IN_F = HID_F = 128, OUT_F = 64

#if defined(__CUDA_ARCH_FEAT_SM103_ALL)
#define HAS_TC 1
#else
#define HAS_TC 0
#endif

#define TOT_TILES ((N_NODES + 127) / 128)  // 782

// ---------------- scratch (device globals; no allocation allowed) ----------
__device__ int    g_deg[N_NODES];
__device__ int    g_off[N_NODES];
__device__ int    g_cur[N_NODES];
__device__ int    g_csr[N_EDGES];
__device__ int    g_bsum[128];
__device__ __half g_sp1s[(size_t)N_NODES * 128];   // feat @ W1_self (fp16)
__device__ __half g_sp1nH[(size_t)N_NODES * 128];  // feat @ W1_neigh (fp16)
__device__ __half g_h[(size_t)N_NODES * 128];      // relu(layer1) (fp16)
__device__ __half g_sp2s[(size_t)N_NODES * 64];    // h @ W2_self (fp16)
__device__ __half g_sp2nH[(size_t)N_NODES * 64];   // h @ W2_neigh (fp16)
__device__ float  g_W1cat[256 * 128];              // B^T layer1: [n][k], n<128 self, else neigh
__device__ float  g_W2cat[128 * 128];              // B^T layer2: [n][k], n<64 self, else neigh

// ---------------- generic helpers -------------------------------------------
__device__ __forceinline__ uint32_t smem_u32(const void* p) {
    uint32_t a;
    asm("{ .reg .u64 t; cvta.to.shared.u64 t, %1; cvt.u32.u64 %0, t; }" : "=r"(a) : "l"(p));
    return a;
}
__device__ __forceinline__ float tf32r(float x) {
    uint32_t u;
    asm("cvt.rna.tf32.f32 %0, %1;" : "=r"(u) : "f"(x));
    return __uint_as_float(u);
}

#if HAS_TC
__device__ __forceinline__ uint32_t elect_one() {
    uint32_t p;
    asm volatile("{ .reg .pred p; elect.sync _|p, 0xFFFFFFFF; selp.b32 %0, 1, 0, p; }" : "=r"(p));
    return p;
}
#define MBAR_INIT(addr, cnt) \
    asm volatile("mbarrier.init.shared.b64 [%0], %1;" :: "r"(addr), "r"(cnt) : "memory")
__device__ __forceinline__ void mbar_wait(uint32_t addr, int phase) {
    asm volatile(
        "{\n\t.reg .pred P;\n\t"
        "WL_%=:\n\t"
        "mbarrier.try_wait.parity.acquire.cta.shared::cta.b64 P, [%0], %1, 0x989680;\n\t"
        "@P bra.uni WD_%=;\n\t"
        "bra.uni WL_%=;\n\t"
        "WD_%=:\n\t}"
        :: "r"(addr), "r"(phase) : "memory");
}
#define TC_ALLOC(ctrl, n) \
    asm volatile("tcgen05.alloc.cta_group::1.sync.aligned.shared::cta.b32 [%0], %1;" :: "r"(ctrl), "r"(n) : "memory")
#define TC_RELINQ() \
    asm volatile("tcgen05.relinquish_alloc_permit.cta_group::1.sync.aligned;")
#define TC_DEALLOC(t, n) \
    asm volatile("tcgen05.dealloc.cta_group::1.sync.aligned.b32 %0, %1;" :: "r"(t), "r"(n))
#define TC_COMMIT(mb) \
    asm volatile("tcgen05.commit.cta_group::1.mbarrier::arrive::one.shared::cluster.b64 [%0];" :: "r"(mb) : "memory")
#define TC_FENCE_AFTER()  asm volatile("tcgen05.fence::after_thread_sync;" ::: "memory")
#define TC_FENCE_BEFORE() asm volatile("tcgen05.fence::before_thread_sync;" ::: "memory")
#define TC_WAIT_LD()      asm volatile("tcgen05.wait::ld.sync.aligned;" ::: "memory")
#define FENCE_ASYNC()     asm volatile("fence.proxy.async.shared::cta;" ::: "memory")

__device__ __forceinline__ void tc_mma_tf32_ss(uint32_t d_tmem, uint64_t a_desc,
                                               uint64_t b_desc, uint32_t idesc, bool acc) {
    uint32_t en = acc ? 1u : 0u;
    asm volatile(
        "{\n\t.reg .pred p;\n\t"
        "setp.ne.u32 p, %4, 0;\n\t"
        "tcgen05.mma.cta_group::1.kind::tf32 [%0], %1, %2, %3, p;\n\t}"
        :: "r"(d_tmem), "l"(a_desc), "l"(b_desc), "r"(idesc), "r"(en) : "memory");
}

#define TC_LD_X32(r, a) \
    asm volatile( \
        "tcgen05.ld.sync.aligned.32x32b.x32.b32 " \
        "{%0,%1,%2,%3,%4,%5,%6,%7,%8,%9,%10,%11,%12,%13,%14,%15," \
        "%16,%17,%18,%19,%20,%21,%22,%23,%24,%25,%26,%27,%28,%29,%30,%31}, [%32];" \
        : "=r"((r)[0]),"=r"((r)[1]),"=r"((r)[2]),"=r"((r)[3]),"=r"((r)[4]),"=r"((r)[5]),"=r"((r)[6]),"=r"((r)[7]), \
          "=r"((r)[8]),"=r"((r)[9]),"=r"((r)[10]),"=r"((r)[11]),"=r"((r)[12]),"=r"((r)[13]),"=r"((r)[14]),"=r"((r)[15]), \
          "=r"((r)[16]),"=r"((r)[17]),"=r"((r)[18]),"=r"((r)[19]),"=r"((r)[20]),"=r"((r)[21]),"=r"((r)[22]),"=r"((r)[23]), \
          "=r"((r)[24]),"=r"((r)[25]),"=r"((r)[26]),"=r"((r)[27]),"=r"((r)[28]),"=r"((r)[29]),"=r"((r)[30]),"=r"((r)[31]) \
        : "r"(a))

// SW128 K-major descriptor: layout=2, version=1, SBO=64, LBO=1
__device__ __forceinline__ uint64_t mk_desc(uint32_t addr) {
    return ((uint64_t)2 << 61) | ((uint64_t)1 << 46) | ((uint64_t)64 << 32) |
           ((uint64_t)1 << 16) | (((uint64_t)addr >> 4) & 0x3FFF);
}

// idesc: dtype=F32, atype=TF32, btype=TF32, N=128, M=128
#define IDESC_TF32 ((1u << 4) | (2u << 7) | (2u << 10) | (16u << 17) | (8u << 24))
#endif  // HAS_TC

// ---------------- CSR build -------------------------------------------------
__global__ void k_zero_deg() {
    int i = blockIdx.x * blockDim.x + threadIdx.x;
    if (i < N_NODES) g_deg[i] = 0;
}

__global__ void k_hist(const int* __restrict__ dst) {
    int i = blockIdx.x * blockDim.x + threadIdx.x;
    if (i < N_EDGES) atomicAdd(&g_deg[dst[i]], 1);
}

__global__ void k_scan1() {
    __shared__ int s[1024];
    int tid = threadIdx.x;
    int i = blockIdx.x * 1024 + tid;
    int v = (i < N_NODES) ? g_deg[i] : 0;
    s[tid] = v;
    __syncthreads();
#pragma unroll
    for (int off = 1; off < 1024; off <<= 1) {
        int t = (tid >= off) ? s[tid - off] : 0;
        __syncthreads();
        s[tid] += t;
        __syncthreads();
    }
    if (i < N_NODES) g_off[i] = s[tid] - v;
    if (tid == 1023) g_bsum[blockIdx.x] = s[tid];
}

__global__ void k_scan2(int nb) {
    __shared__ int s[128];
    int tid = threadIdx.x;
    int v = (tid < nb) ? g_bsum[tid] : 0;
    s[tid] = v;
    __syncthreads();
#pragma unroll
    for (int off = 1; off < 128; off <<= 1) {
        int t = (tid >= off) ? s[tid - off] : 0;
        __syncthreads();
        s[tid] += t;
        __syncthreads();
    }
    if (tid < nb) g_bsum[tid] = s[tid] - v;
}

__global__ void k_scan3() {
    int i = blockIdx.x * blockDim.x + threadIdx.x;
    if (i < N_NODES) {
        int o = g_off[i] + g_bsum[i >> 10];
        g_off[i] = o;
        g_cur[i] = o;
    }
}

__global__ void k_fill(const int* __restrict__ src, const int* __restrict__ dst) {
    int i = blockIdx.x * blockDim.x + threadIdx.x;
    if (i < N_EDGES) {
        int p = atomicAdd(&g_cur[dst[i]], 1);
        g_csr[p] = src[i];
    }
}

// pack both weight matrices transposed ([n][k])
__global__ void k_pack(const float* __restrict__ W1s, const float* __restrict__ W1n,
                       const float* __restrict__ W2s, const float* __restrict__ W2n) {
    int i = blockIdx.x * blockDim.x + threadIdx.x;
    if (i < 256 * 128) {
        int n = i >> 7, k = i & 127;
        g_W1cat[i] = (n < 128) ? W1s[k * 128 + n] : W1n[k * 128 + (n - 128)];
    } else if (i < 256 * 128 + 128 * 128) {
        int j = i - 256 * 128;
        int n = j >> 7, k = j & 127;
        g_W2cat[j] = (n < 64) ? W2s[k * 64 + n] : W2n[k * 64 + (n - 64)];
    }
}

// ---------------- aggregation (warp per destination node) -------------------
// layer1: g_h[v] = relu(sp1s[v] + mean_u sp1nH[u] + b1)
// 2 edges per warp-iteration: lanes 0-15 -> edge e, lanes 16-31 -> edge e+1.
// Each lane loads uint4 = 8 halves at cols (lane&15)*8.
__global__ void k_agg1(const float* __restrict__ b1) {
    int w = (blockIdx.x * blockDim.x + threadIdx.x) >> 5;
    int lane = threadIdx.x & 31;
    if (w >= N_NODES) return;
    int beg = g_off[w];
    int d = g_deg[w];
    int end = beg + d;
    const int colb = (lane & 15) * 8;
    const int half_id = lane >> 4;  // 0 or 1

    float acc[8];
#pragma unroll
    for (int j = 0; j < 8; j++) acc[j] = 0.f;

    int e = beg;
    for (; e + 1 < end; e += 2) {
        int s = g_csr[e + half_id];
        uint4 r = *(const uint4*)(g_sp1nH + (size_t)s * 128 + colb);
#pragma unroll
        for (int q = 0; q < 4; q++) {
            uint32_t u = (&r.x)[q];
            float2 f = __half22float2(*(__half2*)&u);
            acc[q * 2 + 0] += f.x;
            acc[q * 2 + 1] += f.y;
        }
    }
    if (e < end && half_id == 0) {  // odd tail
        int s = g_csr[e];
        uint4 r = *(const uint4*)(g_sp1nH + (size_t)s * 128 + colb);
#pragma unroll
        for (int q = 0; q < 4; q++) {
            uint32_t u = (&r.x)[q];
            float2 f = __half22float2(*(__half2*)&u);
            acc[q * 2 + 0] += f.x;
            acc[q * 2 + 1] += f.y;
        }
    }
    // fold the two half-warps
#pragma unroll
    for (int j = 0; j < 8; j++) acc[j] += __shfl_xor_sync(0xFFFFFFFF, acc[j], 16);

    if (lane < 16) {
        float inv = (d > 0) ? 1.0f / (float)d : 0.0f;
        uint4 sr = *(const uint4*)(g_sp1s + (size_t)w * 128 + colb);
        float4 bb0 = *(const float4*)(b1 + colb);
        float4 bb1 = *(const float4*)(b1 + colb + 4);
        float bv[8] = {bb0.x, bb0.y, bb0.z, bb0.w, bb1.x, bb1.y, bb1.z, bb1.w};
        uint32_t outp[4];
#pragma unroll
        for (int q = 0; q < 4; q++) {
            uint32_t u = (&sr.x)[q];
            float2 s2 = __half22float2(*(__half2*)&u);
            float o0 = fmaxf(s2.x + acc[q * 2 + 0] * inv + bv[q * 2 + 0], 0.f);
            float o1 = fmaxf(s2.y + acc[q * 2 + 1] * inv + bv[q * 2 + 1], 0.f);
            __half2 hh = __floats2half2_rn(o0, o1);
            outp[q] = *(uint32_t*)&hh;
        }
        *(uint4*)(g_h + (size_t)w * 128 + colb) = make_uint4(outp[0], outp[1], outp[2], outp[3]);
    }
}

// layer2: out[v][c] = sp2s[v][c] + mean_u sp2nH[u][c] + b2[c]
// 4 edges per warp-iteration: 8 lanes per edge, each lane loads uint4 = 8 halves.
__global__ void k_agg2(const float* __restrict__ b2, float* __restrict__ out) {
    int w = (blockIdx.x * blockDim.x + threadIdx.x) >> 5;
    int lane = threadIdx.x & 31;
    if (w >= N_NODES) return;
    int beg = g_off[w];
    int d = g_deg[w];
    int end = beg + d;
    const int colb = (lane & 7) * 8;
    const int sub = lane >> 3;  // 0..3

    float acc[8];
#pragma unroll
    for (int j = 0; j < 8; j++) acc[j] = 0.f;

    for (int e = beg; e < end; e += 4) {
        int idx = e + sub;
        if (idx < end) {
            int s = g_csr[idx];
            uint4 r = *(const uint4*)(g_sp2nH + (size_t)s * 64 + colb);
#pragma unroll
            for (int q = 0; q < 4; q++) {
                uint32_t u = (&r.x)[q];
                float2 f = __half22float2(*(__half2*)&u);
                acc[q * 2 + 0] += f.x;
                acc[q * 2 + 1] += f.y;
            }
        }
    }
#pragma unroll
    for (int j = 0; j < 8; j++) {
        acc[j] += __shfl_xor_sync(0xFFFFFFFF, acc[j], 8);
        acc[j] += __shfl_xor_sync(0xFFFFFFFF, acc[j], 16);
    }

    if (lane < 8) {
        float inv = (d > 0) ? 1.0f / (float)d : 0.0f;
        uint4 sr = *(const uint4*)(g_sp2s + (size_t)w * 64 + colb);
        float4 bb0 = *(const float4*)(b2 + colb);
        float4 bb1 = *(const float4*)(b2 + colb + 4);
        float bv[8] = {bb0.x, bb0.y, bb0.z, bb0.w, bb1.x, bb1.y, bb1.z, bb1.w};
        float o[8];
#pragma unroll
        for (int q = 0; q < 4; q++) {
            uint32_t u = (&sr.x)[q];
            float2 s2 = __half22float2(*(__half2*)&u);
            o[q * 2 + 0] = s2.x + acc[q * 2 + 0] * inv + bv[q * 2 + 0];
            o[q * 2 + 1] = s2.y + acc[q * 2 + 1] * inv + bv[q * 2 + 1];
        }
        *(float4*)(out + (size_t)w * 64 + colb)     = make_float4(o[0], o[1], o[2], o[3]);
        *(float4*)(out + (size_t)w * 64 + colb + 4) = make_float4(o[4], o[5], o[6], o[7]);
    }
}

// ---------------- GEMM (tcgen05 on sm_103a; naive fallback otherwise) --------
// LAYER 1 (NT=2): [sp1s | sp1nH](fp16) = feat(fp32) @ W1cat^T  — A 2-term split, B 2-term
// LAYER 2 (NT=1): [sp2s | sp2nH](fp16) = g_h(fp16)  @ W2cat^T  — A exact in tf32, B 2-term
#define GEMM1_SMEM (1024 + 6 * 16384)
#define GEMM2_SMEM (1024 + 3 * 16384)

template <int NT, int LAYER>
__global__ __launch_bounds__(256) void k_gemm(const float* __restrict__ A0) {
    extern __shared__ __align__(1024) char smem[];
    const int tid = threadIdx.x;
    const int row0 = blockIdx.x * 128;
    const float* Wb = (LAYER == 1) ? g_W1cat : g_W2cat;

#if HAS_TC
    const uint32_t sb = smem_u32(smem);
    const uint32_t ctrl = sb;
    const uint32_t mb = sb + 16;
    const uint32_t smAh = sb + 1024;
    const uint32_t smAl = (LAYER == 1) ? smAh + 16384 : 0;  // layer2: no A split
    uint32_t smBh[2], smBl[2];
    uint32_t bbase = (LAYER == 1) ? smAh + 2 * 16384 : smAh + 16384;
    smBh[0] = bbase;
    smBl[0] = bbase + 16384;
    smBh[1] = bbase + 2 * 16384;
    smBl[1] = bbase + 3 * 16384;

    const int wid = tid >> 5;
    const int lane = tid & 31;

    if (wid == 0) {
        TC_ALLOC(ctrl, NT * 128);
        TC_RELINQ();
    }
    if (tid == 0) MBAR_INIT(mb, 1);
    __syncthreads();
    uint32_t tmem;
    asm volatile("ld.shared.b32 %0, [%1];" : "=r"(tmem) : "r"(ctrl));

    int ph = 0;
    for (int c = 0; c < 4; c++) {
        if (c > 0) { mbar_wait(mb, ph); ph ^= 1; }
        const int k0 = c * 32;

#pragma unroll
        for (int i = 0; i < 4; i++) {
            int slot = tid * 4 + i;       // 0..1023
            int rw = slot >> 3;           // 0..127
            int c16 = slot & 7;           // 0..7
            uint32_t bo = rw * 128 + c16 * 16;
            uint32_t sw = bo ^ ((bo >> 3) & 0x70);
            int r = row0 + rw;
            if (LAYER == 1) {
                float4 av = make_float4(0.f, 0.f, 0.f, 0.f);
                if (r < N_NODES) av = *(const float4*)(A0 + (size_t)r * 128 + k0 + c16 * 4);
                float4 ah, al;
                ah.x = tf32r(av.x); al.x = tf32r(av.x - ah.x);
                ah.y = tf32r(av.y); al.y = tf32r(av.y - ah.y);
                ah.z = tf32r(av.z); al.z = tf32r(av.z - ah.z);
                ah.w = tf32r(av.w); al.w = tf32r(av.w - ah.w);
                *(float4*)(smem + (smAh - sb) + sw) = ah;
                *(float4*)(smem + (smAl - sb) + sw) = al;
            } else {
                // fp16 A: exact in tf32, single tile
                float4 ah = make_float4(0.f, 0.f, 0.f, 0.f);
                if (r < N_NODES) {
                    uint2 hv = *(const uint2*)(g_h + (size_t)r * 128 + k0 + c16 * 4);
                    float2 f0 = __half22float2(*(__half2*)&hv.x);
                    float2 f1 = __half22float2(*(__half2*)&hv.y);
                    ah = make_float4(f0.x, f0.y, f1.x, f1.y);
                }
                *(float4*)(smem + (smAh - sb) + sw) = ah;
            }
            // B tiles (fp32 weights, hi/lo split)
#pragma unroll
            for (int nt = 0; nt < NT; nt++) {
                float4 bv = *(const float4*)(Wb + (size_t)(nt * 128 + rw) * 128 + k0 + c16 * 4);
                float4 bh, bl;
                bh.x = tf32r(bv.x); bl.x = tf32r(bv.x - bh.x);
                bh.y = tf32r(bv.y); bl.y = tf32r(bv.y - bh.y);
                bh.z = tf32r(bv.z); bl.z = tf32r(bv.z - bh.z);
                bh.w = tf32r(bv.w); bl.w = tf32r(bv.w - bh.w);
                *(float4*)(smem + (smBh[nt] - sb) + sw) = bh;
                *(float4*)(smem + (smBl[nt] - sb) + sw) = bl;
            }
        }
        FENCE_ASYNC();
        __syncthreads();
        if (wid == 0) {
            if (elect_one()) {
                uint64_t adh = mk_desc(smAh);
                uint64_t adl = (LAYER == 1) ? mk_desc(smAl) : 0;
#pragma unroll
                for (int nt = 0; nt < NT; nt++) {
                    uint64_t bdh = mk_desc(smBh[nt]), bdl = mk_desc(smBl[nt]);
                    uint32_t dt = tmem + nt * 128;
#pragma unroll
                    for (int s = 0; s < 4; s++) {
                        tc_mma_tf32_ss(dt, adh + s * 2, bdh + s * 2, IDESC_TF32, !(c == 0 && s == 0));
                        tc_mma_tf32_ss(dt, adh + s * 2, bdl + s * 2, IDESC_TF32, true);
                        if (LAYER == 1)
                            tc_mma_tf32_ss(dt, adl + s * 2, bdh + s * 2, IDESC_TF32, true);
                    }
                }
                TC_COMMIT(mb);
            }
        }
    }
    mbar_wait(mb, ph);
    TC_FENCE_AFTER();

    // epilogue: warps 0..3 each cover 32 M-rows; all outputs fp16
    if (wid < 4) {
        int r = row0 + wid * 32 + lane;
        const int NCOL = (LAYER == 1) ? 128 : 64;  // per half
        __half* dst_s = (LAYER == 1) ? g_sp1s : g_sp2s;
        __half* dst_n = (LAYER == 1) ? g_sp1nH : g_sp2nH;
#pragma unroll
        for (int half = 0; half < 2; half++) {
            __half* D = half ? dst_n : dst_s;
            int tb = half * NCOL;
            for (int off = 0; off < NCOL; off += 32) {
                uint32_t dr[32];
                TC_LD_X32(dr, tmem + tb + off);
                TC_WAIT_LD();
                if (r < N_NODES) {
                    uint32_t pk[16];
#pragma unroll
                    for (int q = 0; q < 16; q++) {
                        __half2 hh = __floats2half2_rn(__uint_as_float(dr[2 * q]),
                                                       __uint_as_float(dr[2 * q + 1]));
                        pk[q] = *(uint32_t*)&hh;
                    }
#pragma unroll
                    for (int q = 0; q < 4; q++)
                        *(uint4*)(D + (size_t)r * NCOL + off + q * 8) =
                            make_uint4(pk[q * 4], pk[q * 4 + 1], pk[q * 4 + 2], pk[q * 4 + 3]);
                }
            }
        }
        TC_FENCE_BEFORE();
    }
    __syncthreads();
    if (wid == 0) TC_DEALLOC(tmem, NT * 128);

#else  // ---------------- naive fallback (non-sm_103a pass; never runs on GB300)
    for (int e = tid; e < 128 * NT * 128; e += 256) {
        int rr = e / (NT * 128);
        int cc = e % (NT * 128);
        int r = row0 + rr;
        if (r >= N_NODES) continue;
        float s = 0.f;
        if (LAYER == 1) {
            const float* Arow = A0 + (size_t)r * 128;
            const float* Brow = Wb + (size_t)cc * 128;
            for (int k = 0; k < 128; k++) s += Arow[k] * Brow[k];
            if (cc < 128) g_sp1s[(size_t)r * 128 + cc] = __float2half_rn(s);
            else          g_sp1nH[(size_t)r * 128 + (cc - 128)] = __float2half_rn(s);
        } else {
            const __half* Arow = g_h + (size_t)r * 128;
            const float* Brow = Wb + (size_t)cc * 128;
            for (int k = 0; k < 128; k++) s += __half2float(Arow[k]) * Brow[k];
            if (cc < 64) g_sp2s[(size_t)r * 64 + cc] = __float2half_rn(s);
            else         g_sp2nH[(size_t)r * 64 + (cc - 64)] = __float2half_rn(s);
        }
    }
#endif
}

// ---------------- launch -----------------------------------------------------
extern "C" void kernel_launch(void* const* d_in, const int* in_sizes, int n_in,
                              void* d_out, int out_size) {
    const float* feat = (const float*)d_in[0];
    const int*   esrc = (const int*)d_in[1];
    const int*   edst = (const int*)d_in[2];
    const float* W1s  = (const float*)d_in[3];
    const float* W1n  = (const float*)d_in[4];
    const float* b1   = (const float*)d_in[5];
    const float* W2s  = (const float*)d_in[6];
    const float* W2n  = (const float*)d_in[7];
    const float* b2   = (const float*)d_in[8];
    float* out = (float*)d_out;

    static cudaStream_t s1 = nullptr;
    static cudaEvent_t e0 = nullptr, e1 = nullptr;
    if (!s1) {
        cudaStreamCreateWithFlags(&s1, cudaStreamNonBlocking);
        cudaEventCreateWithFlags(&e0, cudaEventDisableTiming);
        cudaEventCreateWithFlags(&e1, cudaEventDisableTiming);
    }

    cudaFuncSetAttribute(k_gemm<2, 1>, cudaFuncAttributeMaxDynamicSharedMemorySize, GEMM1_SMEM);
    cudaFuncSetAttribute(k_gemm<1, 2>, cudaFuncAttributeMaxDynamicSharedMemorySize, GEMM2_SMEM);

    const int TB = 256;

    // ---- fork: stream s1 does pack + layer-1 projection GEMM (graph-independent)
    cudaEventRecord(e0, 0);
    cudaStreamWaitEvent(s1, e0, 0);
    k_pack<<<(256 * 128 + 128 * 128 + TB - 1) / TB, TB, 0, s1>>>(W1s, W1n, W2s, W2n);
    k_gemm<2, 1><<<TOT_TILES, 256, GEMM1_SMEM, s1>>>(feat);
    cudaEventRecord(e1, s1);

    // ---- default stream: CSR build
    k_zero_deg<<<(N_NODES + TB - 1) / TB, TB>>>();
    k_hist<<<(N_EDGES + TB - 1) / TB, TB>>>(edst);
    int nb = (N_NODES + 1023) / 1024;  // 98
    k_scan1<<<nb, 1024>>>();
    k_scan2<<<1, 128>>>(nb);
    k_scan3<<<(N_NODES + TB - 1) / TB, TB>>>();
    k_fill<<<(N_EDGES + TB - 1) / TB, TB>>>(esrc, edst);

    // ---- join
    cudaStreamWaitEvent(0, e1, 0);

    // layer 1 aggregate (+self+bias+relu), layer 2 projection, layer 2 aggregate
    k_agg1<<<(N_NODES * 32 + TB - 1) / TB, TB>>>(b1);
    k_gemm<1, 2><<<TOT_TILES, 256, GEMM2_SMEM>>>(nullptr);
    k_agg2<<<(N_NODES * 32 + TB - 1) / TB, TB>>>(b2, out);
}

// round 8
// speedup vs baseline: 2.2858x; 1.0482x over previous
#include <cuda_runtime.h>
#include <cuda_fp16.h>
#include <cstdint>

#define N_NODES 100000
#define N_EDGES 1600000
// IN_F = HID_F = 128, OUT_F = 64

#if defined(__CUDA_ARCH_FEAT_SM103_ALL)
#define HAS_TC 1
#else
#define HAS_TC 0
#endif

#define TOT_TILES ((N_NODES + 127) / 128)  // 782

// ---------------- scratch (device globals; no allocation allowed) ----------
__device__ int    g_deg[N_NODES];
__device__ int    g_off[N_NODES];
__device__ int    g_cur[N_NODES];
__device__ int    g_csr[N_EDGES];
__device__ int    g_bsum[128];
__device__ __half g_featH[(size_t)N_NODES * 128];  // feat (fp16)
__device__ __half g_sp1s[(size_t)N_NODES * 128];   // feat @ W1_self (fp16)
__device__ __half g_sp1nH[(size_t)N_NODES * 128];  // feat @ W1_neigh (fp16)
__device__ __half g_h[(size_t)N_NODES * 128];      // relu(layer1) (fp16)
__device__ __half g_sp2s[(size_t)N_NODES * 64];    // h @ W2_self (fp16)
__device__ __half g_sp2nH[(size_t)N_NODES * 64];   // h @ W2_neigh (fp16)
__device__ float  g_W1cat[256 * 128];              // B^T layer1: [n][k], n<128 self, else neigh
__device__ float  g_W2cat[128 * 128];              // B^T layer2: [n][k], n<64 self, else neigh

// ---------------- generic helpers -------------------------------------------
__device__ __forceinline__ uint32_t smem_u32(const void* p) {
    uint32_t a;
    asm("{ .reg .u64 t; cvta.to.shared.u64 t, %1; cvt.u32.u64 %0, t; }" : "=r"(a) : "l"(p));
    return a;
}
__device__ __forceinline__ float tf32r(float x) {
    uint32_t u;
    asm("cvt.rna.tf32.f32 %0, %1;" : "=r"(u) : "f"(x));
    return __uint_as_float(u);
}

#if HAS_TC
__device__ __forceinline__ uint32_t elect_one() {
    uint32_t p;
    asm volatile("{ .reg .pred p; elect.sync _|p, 0xFFFFFFFF; selp.b32 %0, 1, 0, p; }" : "=r"(p));
    return p;
}
#define MBAR_INIT(addr, cnt) \
    asm volatile("mbarrier.init.shared.b64 [%0], %1;" :: "r"(addr), "r"(cnt) : "memory")
__device__ __forceinline__ void mbar_wait(uint32_t addr, int phase) {
    asm volatile(
        "{\n\t.reg .pred P;\n\t"
        "WL_%=:\n\t"
        "mbarrier.try_wait.parity.acquire.cta.shared::cta.b64 P, [%0], %1, 0x989680;\n\t"
        "@P bra.uni WD_%=;\n\t"
        "bra.uni WL_%=;\n\t"
        "WD_%=:\n\t}"
        :: "r"(addr), "r"(phase) : "memory");
}
#define TC_ALLOC(ctrl, n) \
    asm volatile("tcgen05.alloc.cta_group::1.sync.aligned.shared::cta.b32 [%0], %1;" :: "r"(ctrl), "r"(n) : "memory")
#define TC_RELINQ() \
    asm volatile("tcgen05.relinquish_alloc_permit.cta_group::1.sync.aligned;")
#define TC_DEALLOC(t, n) \
    asm volatile("tcgen05.dealloc.cta_group::1.sync.aligned.b32 %0, %1;" :: "r"(t), "r"(n))
#define TC_COMMIT(mb) \
    asm volatile("tcgen05.commit.cta_group::1.mbarrier::arrive::one.shared::cluster.b64 [%0];" :: "r"(mb) : "memory")
#define TC_FENCE_AFTER()  asm volatile("tcgen05.fence::after_thread_sync;" ::: "memory")
#define TC_FENCE_BEFORE() asm volatile("tcgen05.fence::before_thread_sync;" ::: "memory")
#define TC_WAIT_LD()      asm volatile("tcgen05.wait::ld.sync.aligned;" ::: "memory")
#define FENCE_ASYNC()     asm volatile("fence.proxy.async.shared::cta;" ::: "memory")

__device__ __forceinline__ void tc_mma_tf32_ss(uint32_t d_tmem, uint64_t a_desc,
                                               uint64_t b_desc, uint32_t idesc, bool acc) {
    uint32_t en = acc ? 1u : 0u;
    asm volatile(
        "{\n\t.reg .pred p;\n\t"
        "setp.ne.u32 p, %4, 0;\n\t"
        "tcgen05.mma.cta_group::1.kind::tf32 [%0], %1, %2, %3, p;\n\t}"
        :: "r"(d_tmem), "l"(a_desc), "l"(b_desc), "r"(idesc), "r"(en) : "memory");
}

#define TC_LD_X32(r, a) \
    asm volatile( \
        "tcgen05.ld.sync.aligned.32x32b.x32.b32 " \
        "{%0,%1,%2,%3,%4,%5,%6,%7,%8,%9,%10,%11,%12,%13,%14,%15," \
        "%16,%17,%18,%19,%20,%21,%22,%23,%24,%25,%26,%27,%28,%29,%30,%31}, [%32];" \
        : "=r"((r)[0]),"=r"((r)[1]),"=r"((r)[2]),"=r"((r)[3]),"=r"((r)[4]),"=r"((r)[5]),"=r"((r)[6]),"=r"((r)[7]), \
          "=r"((r)[8]),"=r"((r)[9]),"=r"((r)[10]),"=r"((r)[11]),"=r"((r)[12]),"=r"((r)[13]),"=r"((r)[14]),"=r"((r)[15]), \
          "=r"((r)[16]),"=r"((r)[17]),"=r"((r)[18]),"=r"((r)[19]),"=r"((r)[20]),"=r"((r)[21]),"=r"((r)[22]),"=r"((r)[23]), \
          "=r"((r)[24]),"=r"((r)[25]),"=r"((r)[26]),"=r"((r)[27]),"=r"((r)[28]),"=r"((r)[29]),"=r"((r)[30]),"=r"((r)[31]) \
        : "r"(a))

// SW128 K-major descriptor: layout=2, version=1, SBO=64, LBO=1
__device__ __forceinline__ uint64_t mk_desc(uint32_t addr) {
    return ((uint64_t)2 << 61) | ((uint64_t)1 << 46) | ((uint64_t)64 << 32) |
           ((uint64_t)1 << 16) | (((uint64_t)addr >> 4) & 0x3FFF);
}

// idesc: dtype=F32, atype=TF32, btype=TF32, N=128, M=128
#define IDESC_TF32 ((1u << 4) | (2u << 7) | (2u << 10) | (16u << 17) | (8u << 24))
#endif  // HAS_TC

// ---------------- CSR build -------------------------------------------------
__global__ void k_zero_deg() {
    int i = blockIdx.x * blockDim.x + threadIdx.x;
    if (i < N_NODES) g_deg[i] = 0;
}

__global__ void k_hist(const int* __restrict__ dst) {
    int i = blockIdx.x * blockDim.x + threadIdx.x;
    if (i < N_EDGES) atomicAdd(&g_deg[dst[i]], 1);
}

__global__ void k_scan1() {
    __shared__ int s[1024];
    int tid = threadIdx.x;
    int i = blockIdx.x * 1024 + tid;
    int v = (i < N_NODES) ? g_deg[i] : 0;
    s[tid] = v;
    __syncthreads();
#pragma unroll
    for (int off = 1; off < 1024; off <<= 1) {
        int t = (tid >= off) ? s[tid - off] : 0;
        __syncthreads();
        s[tid] += t;
        __syncthreads();
    }
    if (i < N_NODES) g_off[i] = s[tid] - v;
    if (tid == 1023) g_bsum[blockIdx.x] = s[tid];
}

__global__ void k_scan2(int nb) {
    __shared__ int s[128];
    int tid = threadIdx.x;
    int v = (tid < nb) ? g_bsum[tid] : 0;
    s[tid] = v;
    __syncthreads();
#pragma unroll
    for (int off = 1; off < 128; off <<= 1) {
        int t = (tid >= off) ? s[tid - off] : 0;
        __syncthreads();
        s[tid] += t;
        __syncthreads();
    }
    if (tid < nb) g_bsum[tid] = s[tid] - v;
}

__global__ void k_scan3() {
    int i = blockIdx.x * blockDim.x + threadIdx.x;
    if (i < N_NODES) {
        int o = g_off[i] + g_bsum[i >> 10];
        g_off[i] = o;
        g_cur[i] = o;
    }
}

__global__ void k_fill(const int* __restrict__ src, const int* __restrict__ dst) {
    int i = blockIdx.x * blockDim.x + threadIdx.x;
    if (i < N_EDGES) {
        int p = atomicAdd(&g_cur[dst[i]], 1);
        g_csr[p] = src[i];
    }
}

// feat fp32 -> fp16 (each thread converts 8 values)
__global__ void k_cvt(const float* __restrict__ feat) {
    int i = blockIdx.x * blockDim.x + threadIdx.x;
    if (i < N_NODES * 16) {
        const float4* p = (const float4*)feat + (size_t)i * 2;
        float4 a = p[0], b = p[1];
        __half2 h0 = __floats2half2_rn(a.x, a.y);
        __half2 h1 = __floats2half2_rn(a.z, a.w);
        __half2 h2 = __floats2half2_rn(b.x, b.y);
        __half2 h3 = __floats2half2_rn(b.z, b.w);
        *(uint4*)(g_featH + (size_t)i * 8) =
            make_uint4(*(uint32_t*)&h0, *(uint32_t*)&h1, *(uint32_t*)&h2, *(uint32_t*)&h3);
    }
}

// pack both weight matrices transposed ([n][k])
__global__ void k_pack(const float* __restrict__ W1s, const float* __restrict__ W1n,
                       const float* __restrict__ W2s, const float* __restrict__ W2n) {
    int i = blockIdx.x * blockDim.x + threadIdx.x;
    if (i < 256 * 128) {
        int n = i >> 7, k = i & 127;
        g_W1cat[i] = (n < 128) ? W1s[k * 128 + n] : W1n[k * 128 + (n - 128)];
    } else if (i < 256 * 128 + 128 * 128) {
        int j = i - 256 * 128;
        int n = j >> 7, k = j & 127;
        g_W2cat[j] = (n < 64) ? W2s[k * 64 + n] : W2n[k * 64 + (n - 64)];
    }
}

// ---------------- aggregation (warp per destination node) -------------------
// layer1: g_h[v] = relu(sp1s[v] + mean_u sp1nH[u] + b1)
// 4 edges per main iteration (2 independent LDG.128 in flight per lane).
__global__ void k_agg1(const float* __restrict__ b1) {
    int w = (blockIdx.x * blockDim.x + threadIdx.x) >> 5;
    int lane = threadIdx.x & 31;
    if (w >= N_NODES) return;
    int beg = g_off[w];
    int d = g_deg[w];
    int end = beg + d;
    const int colb = (lane & 15) * 8;
    const int half_id = lane >> 4;  // 0 or 1

    float acc[8];
#pragma unroll
    for (int j = 0; j < 8; j++) acc[j] = 0.f;

    int e = beg;
    for (; e + 3 < end; e += 4) {
        int s0 = g_csr[e + half_id];
        int s1 = g_csr[e + 2 + half_id];
        uint4 r0 = *(const uint4*)(g_sp1nH + (size_t)s0 * 128 + colb);
        uint4 r1 = *(const uint4*)(g_sp1nH + (size_t)s1 * 128 + colb);
#pragma unroll
        for (int q = 0; q < 4; q++) {
            uint32_t u0 = (&r0.x)[q];
            uint32_t u1 = (&r1.x)[q];
            float2 f0 = __half22float2(*(__half2*)&u0);
            float2 f1 = __half22float2(*(__half2*)&u1);
            acc[q * 2 + 0] += f0.x + f1.x;
            acc[q * 2 + 1] += f0.y + f1.y;
        }
    }
    for (; e + 1 < end; e += 2) {
        int s0 = g_csr[e + half_id];
        uint4 r0 = *(const uint4*)(g_sp1nH + (size_t)s0 * 128 + colb);
#pragma unroll
        for (int q = 0; q < 4; q++) {
            uint32_t u0 = (&r0.x)[q];
            float2 f0 = __half22float2(*(__half2*)&u0);
            acc[q * 2 + 0] += f0.x;
            acc[q * 2 + 1] += f0.y;
        }
    }
    if (e < end && half_id == 0) {  // odd tail
        int s0 = g_csr[e];
        uint4 r0 = *(const uint4*)(g_sp1nH + (size_t)s0 * 128 + colb);
#pragma unroll
        for (int q = 0; q < 4; q++) {
            uint32_t u0 = (&r0.x)[q];
            float2 f0 = __half22float2(*(__half2*)&u0);
            acc[q * 2 + 0] += f0.x;
            acc[q * 2 + 1] += f0.y;
        }
    }
#pragma unroll
    for (int j = 0; j < 8; j++) acc[j] += __shfl_xor_sync(0xFFFFFFFF, acc[j], 16);

    if (lane < 16) {
        float inv = (d > 0) ? 1.0f / (float)d : 0.0f;
        uint4 sr = *(const uint4*)(g_sp1s + (size_t)w * 128 + colb);
        float4 bb0 = *(const float4*)(b1 + colb);
        float4 bb1 = *(const float4*)(b1 + colb + 4);
        float bv[8] = {bb0.x, bb0.y, bb0.z, bb0.w, bb1.x, bb1.y, bb1.z, bb1.w};
        uint32_t outp[4];
#pragma unroll
        for (int q = 0; q < 4; q++) {
            uint32_t u = (&sr.x)[q];
            float2 s2 = __half22float2(*(__half2*)&u);
            float o0 = fmaxf(s2.x + acc[q * 2 + 0] * inv + bv[q * 2 + 0], 0.f);
            float o1 = fmaxf(s2.y + acc[q * 2 + 1] * inv + bv[q * 2 + 1], 0.f);
            __half2 hh = __floats2half2_rn(o0, o1);
            outp[q] = *(uint32_t*)&hh;
        }
        *(uint4*)(g_h + (size_t)w * 128 + colb) = make_uint4(outp[0], outp[1], outp[2], outp[3]);
    }
}

// layer2: out[v][c] = sp2s[v][c] + mean_u sp2nH[u][c] + b2[c]
// 8 edges per main iteration (2 independent LDG.128 in flight per lane).
__global__ void k_agg2(const float* __restrict__ b2, float* __restrict__ out) {
    int w = (blockIdx.x * blockDim.x + threadIdx.x) >> 5;
    int lane = threadIdx.x & 31;
    if (w >= N_NODES) return;
    int beg = g_off[w];
    int d = g_deg[w];
    int end = beg + d;
    const int colb = (lane & 7) * 8;
    const int sub = lane >> 3;  // 0..3

    float acc[8];
#pragma unroll
    for (int j = 0; j < 8; j++) acc[j] = 0.f;

    int e = beg;
    for (; e + 7 < end; e += 8) {
        int s0 = g_csr[e + sub];
        int s1 = g_csr[e + 4 + sub];
        uint4 r0 = *(const uint4*)(g_sp2nH + (size_t)s0 * 64 + colb);
        uint4 r1 = *(const uint4*)(g_sp2nH + (size_t)s1 * 64 + colb);
#pragma unroll
        for (int q = 0; q < 4; q++) {
            uint32_t u0 = (&r0.x)[q];
            uint32_t u1 = (&r1.x)[q];
            float2 f0 = __half22float2(*(__half2*)&u0);
            float2 f1 = __half22float2(*(__half2*)&u1);
            acc[q * 2 + 0] += f0.x + f1.x;
            acc[q * 2 + 1] += f0.y + f1.y;
        }
    }
    for (; e < end; e += 4) {
        int idx = e + sub;
        if (idx < end) {
            int s = g_csr[idx];
            uint4 r = *(const uint4*)(g_sp2nH + (size_t)s * 64 + colb);
#pragma unroll
            for (int q = 0; q < 4; q++) {
                uint32_t u = (&r.x)[q];
                float2 f = __half22float2(*(__half2*)&u);
                acc[q * 2 + 0] += f.x;
                acc[q * 2 + 1] += f.y;
            }
        }
    }
#pragma unroll
    for (int j = 0; j < 8; j++) {
        acc[j] += __shfl_xor_sync(0xFFFFFFFF, acc[j], 8);
        acc[j] += __shfl_xor_sync(0xFFFFFFFF, acc[j], 16);
    }

    if (lane < 8) {
        float inv = (d > 0) ? 1.0f / (float)d : 0.0f;
        uint4 sr = *(const uint4*)(g_sp2s + (size_t)w * 64 + colb);
        float4 bb0 = *(const float4*)(b2 + colb);
        float4 bb1 = *(const float4*)(b2 + colb + 4);
        float bv[8] = {bb0.x, bb0.y, bb0.z, bb0.w, bb1.x, bb1.y, bb1.z, bb1.w};
        float o[8];
#pragma unroll
        for (int q = 0; q < 4; q++) {
            uint32_t u = (&sr.x)[q];
            float2 s2 = __half22float2(*(__half2*)&u);
            o[q * 2 + 0] = s2.x + acc[q * 2 + 0] * inv + bv[q * 2 + 0];
            o[q * 2 + 1] = s2.y + acc[q * 2 + 1] * inv + bv[q * 2 + 1];
        }
        *(float4*)(out + (size_t)w * 64 + colb)     = make_float4(o[0], o[1], o[2], o[3]);
        *(float4*)(out + (size_t)w * 64 + colb + 4) = make_float4(o[4], o[5], o[6], o[7]);
    }
}

// ---------------- GEMM (tcgen05 on sm_103a; naive fallback otherwise) --------
// A is fp16 (exact in tf32, single tile). B fp32 weights with hi/lo split.
// LAYER 1 (NT=2): [sp1s | sp1nH](fp16) = g_featH @ W1cat^T
// LAYER 2 (NT=1): [sp2s | sp2nH](fp16) = g_h     @ W2cat^T
#define GEMM1_SMEM (1024 + 5 * 16384)
#define GEMM2_SMEM (1024 + 3 * 16384)

template <int NT, int LAYER>
__global__ __launch_bounds__(256) void k_gemm() {
    extern __shared__ __align__(1024) char smem[];
    const int tid = threadIdx.x;
    const int row0 = blockIdx.x * 128;
    const float* Wb = (LAYER == 1) ? g_W1cat : g_W2cat;
    const __half* Ah = (LAYER == 1) ? g_featH : g_h;

#if HAS_TC
    const uint32_t sb = smem_u32(smem);
    const uint32_t ctrl = sb;
    const uint32_t mb = sb + 16;
    const uint32_t smA = sb + 1024;
    uint32_t smBh[2], smBl[2];
    smBh[0] = smA + 16384;
    smBl[0] = smBh[0] + 16384;
    smBh[1] = smBl[0] + 16384;
    smBl[1] = smBh[1] + 16384;

    const int wid = tid >> 5;
    const int lane = tid & 31;

    if (wid == 0) {
        TC_ALLOC(ctrl, NT * 128);
        TC_RELINQ();
    }
    if (tid == 0) MBAR_INIT(mb, 1);
    __syncthreads();
    uint32_t tmem;
    asm volatile("ld.shared.b32 %0, [%1];" : "=r"(tmem) : "r"(ctrl));

    int ph = 0;
    for (int c = 0; c < 4; c++) {
        if (c > 0) { mbar_wait(mb, ph); ph ^= 1; }
        const int k0 = c * 32;

#pragma unroll
        for (int i = 0; i < 4; i++) {
            int slot = tid * 4 + i;       // 0..1023
            int rw = slot >> 3;           // 0..127
            int c16 = slot & 7;           // 0..7
            uint32_t bo = rw * 128 + c16 * 16;
            uint32_t sw = bo ^ ((bo >> 3) & 0x70);
            int r = row0 + rw;
            // A: fp16 -> fp32 (exact), single tile
            float4 av = make_float4(0.f, 0.f, 0.f, 0.f);
            if (r < N_NODES) {
                uint2 hv = *(const uint2*)(Ah + (size_t)r * 128 + k0 + c16 * 4);
                float2 f0 = __half22float2(*(__half2*)&hv.x);
                float2 f1 = __half22float2(*(__half2*)&hv.y);
                av = make_float4(f0.x, f0.y, f1.x, f1.y);
            }
            *(float4*)(smem + (smA - sb) + sw) = av;
            // B tiles (fp32 weights, hi/lo split)
#pragma unroll
            for (int nt = 0; nt < NT; nt++) {
                float4 bv = *(const float4*)(Wb + (size_t)(nt * 128 + rw) * 128 + k0 + c16 * 4);
                float4 bh, bl;
                bh.x = tf32r(bv.x); bl.x = tf32r(bv.x - bh.x);
                bh.y = tf32r(bv.y); bl.y = tf32r(bv.y - bh.y);
                bh.z = tf32r(bv.z); bl.z = tf32r(bv.z - bh.z);
                bh.w = tf32r(bv.w); bl.w = tf32r(bv.w - bh.w);
                *(float4*)(smem + (smBh[nt] - sb) + sw) = bh;
                *(float4*)(smem + (smBl[nt] - sb) + sw) = bl;
            }
        }
        FENCE_ASYNC();
        __syncthreads();
        if (wid == 0) {
            if (elect_one()) {
                uint64_t ad = mk_desc(smA);
#pragma unroll
                for (int nt = 0; nt < NT; nt++) {
                    uint64_t bdh = mk_desc(smBh[nt]), bdl = mk_desc(smBl[nt]);
                    uint32_t dt = tmem + nt * 128;
#pragma unroll
                    for (int s = 0; s < 4; s++) {
                        tc_mma_tf32_ss(dt, ad + s * 2, bdh + s * 2, IDESC_TF32, !(c == 0 && s == 0));
                        tc_mma_tf32_ss(dt, ad + s * 2, bdl + s * 2, IDESC_TF32, true);
                    }
                }
                TC_COMMIT(mb);
            }
        }
    }
    mbar_wait(mb, ph);
    TC_FENCE_AFTER();

    // epilogue: warps 0..3 each cover 32 M-rows; paired tcgen05.ld, one wait per 64 cols
    if (wid < 4) {
        int r = row0 + wid * 32 + lane;
        const int NCOL = (LAYER == 1) ? 128 : 64;  // per half
        __half* dst_s = (LAYER == 1) ? g_sp1s : g_sp2s;
        __half* dst_n = (LAYER == 1) ? g_sp1nH : g_sp2nH;
#pragma unroll
        for (int half = 0; half < 2; half++) {
            __half* D = half ? dst_n : dst_s;
            int tb = half * NCOL;
#pragma unroll
            for (int off = 0; off < NCOL; off += 64) {
                uint32_t dr0[32], dr1[32];
                TC_LD_X32(dr0, tmem + tb + off);
                TC_LD_X32(dr1, tmem + tb + off + 32);
                TC_WAIT_LD();
                if (r < N_NODES) {
                    uint32_t pk[32];
#pragma unroll
                    for (int q = 0; q < 16; q++) {
                        __half2 h0 = __floats2half2_rn(__uint_as_float(dr0[2 * q]),
                                                       __uint_as_float(dr0[2 * q + 1]));
                        __half2 h1 = __floats2half2_rn(__uint_as_float(dr1[2 * q]),
                                                       __uint_as_float(dr1[2 * q + 1]));
                        pk[q] = *(uint32_t*)&h0;
                        pk[16 + q] = *(uint32_t*)&h1;
                    }
#pragma unroll
                    for (int q = 0; q < 8; q++)
                        *(uint4*)(D + (size_t)r * NCOL + off + q * 8) =
                            make_uint4(pk[q * 4], pk[q * 4 + 1], pk[q * 4 + 2], pk[q * 4 + 3]);
                }
            }
        }
        TC_FENCE_BEFORE();
    }
    __syncthreads();
    if (wid == 0) TC_DEALLOC(tmem, NT * 128);

#else  // ---------------- naive fallback (non-sm_103a pass; never runs on GB300)
    for (int e = tid; e < 128 * NT * 128; e += 256) {
        int rr = e / (NT * 128);
        int cc = e % (NT * 128);
        int r = row0 + rr;
        if (r >= N_NODES) continue;
        const __half* Arow = Ah + (size_t)r * 128;
        const float* Brow = Wb + (size_t)cc * 128;
        float s = 0.f;
        for (int k = 0; k < 128; k++) s += __half2float(Arow[k]) * Brow[k];
        if (LAYER == 1) {
            if (cc < 128) g_sp1s[(size_t)r * 128 + cc] = __float2half_rn(s);
            else          g_sp1nH[(size_t)r * 128 + (cc - 128)] = __float2half_rn(s);
        } else {
            if (cc < 64) g_sp2s[(size_t)r * 64 + cc] = __float2half_rn(s);
            else         g_sp2nH[(size_t)r * 64 + (cc - 64)] = __float2half_rn(s);
        }
    }
#endif
}

// ---------------- launch -----------------------------------------------------
extern "C" void kernel_launch(void* const* d_in, const int* in_sizes, int n_in,
                              void* d_out, int out_size) {
    const float* feat = (const float*)d_in[0];
    const int*   esrc = (const int*)d_in[1];
    const int*   edst = (const int*)d_in[2];
    const float* W1s  = (const float*)d_in[3];
    const float* W1n  = (const float*)d_in[4];
    const float* b1   = (const float*)d_in[5];
    const float* W2s  = (const float*)d_in[6];
    const float* W2n  = (const float*)d_in[7];
    const float* b2   = (const float*)d_in[8];
    float* out = (float*)d_out;

    static cudaStream_t s1 = nullptr;
    static cudaEvent_t e0 = nullptr, e1 = nullptr;
    if (!s1) {
        cudaStreamCreateWithFlags(&s1, cudaStreamNonBlocking);
        cudaEventCreateWithFlags(&e0, cudaEventDisableTiming);
        cudaEventCreateWithFlags(&e1, cudaEventDisableTiming);
    }

    cudaFuncSetAttribute(k_gemm<2, 1>, cudaFuncAttributeMaxDynamicSharedMemorySize, GEMM1_SMEM);
    cudaFuncSetAttribute(k_gemm<1, 2>, cudaFuncAttributeMaxDynamicSharedMemorySize, GEMM2_SMEM);

    const int TB = 256;

    // ---- fork: stream s1 does cvt + pack + layer-1 projection GEMM (graph-independent)
    cudaEventRecord(e0, 0);
    cudaStreamWaitEvent(s1, e0, 0);
    k_cvt<<<(N_NODES * 16 + TB - 1) / TB, TB, 0, s1>>>(feat);
    k_pack<<<(256 * 128 + 128 * 128 + TB - 1) / TB, TB, 0, s1>>>(W1s, W1n, W2s, W2n);
    k_gemm<2, 1><<<TOT_TILES, 256, GEMM1_SMEM, s1>>>();
    cudaEventRecord(e1, s1);

    // ---- default stream: CSR build
    k_zero_deg<<<(N_NODES + TB - 1) / TB, TB>>>();
    k_hist<<<(N_EDGES + TB - 1) / TB, TB>>>(edst);
    int nb = (N_NODES + 1023) / 1024;  // 98
    k_scan1<<<nb, 1024>>>();
    k_scan2<<<1, 128>>>(nb);
    k_scan3<<<(N_NODES + TB - 1) / TB, TB>>>();
    k_fill<<<(N_EDGES + TB - 1) / TB, TB>>>(esrc, edst);

    // ---- join
    cudaStreamWaitEvent(0, e1, 0);

    // layer 1 aggregate (+self+bias+relu), layer 2 projection, layer 2 aggregate
    k_agg1<<<(N_NODES * 32 + TB - 1) / TB, TB>>>(b1);
    k_gemm<1, 2><<<TOT_TILES, 256, GEMM2_SMEM>>>();
    k_agg2<<<(N_NODES * 32 + TB - 1) / TB, TB>>>(b2, out);
}